// round 1
// baseline (speedup 1.0000x reference)
#include <cuda_runtime.h>
#include <math.h>

#define NN 32768
#define EE 131072
#define HH 6
#define CC 128
#define LL 6
#define GG 2048

// ---------------- scratch (device globals; no allocation allowed) ------------
__device__ float g_x[NN*CC];        // 16 MB
__device__ float g_xn[NN*CC];       // 16 MB
__device__ float g_q[NN*HH*CC];     // 96 MB
__device__ float g_k[NN*HH*CC];     // 96 MB
__device__ float g_v[NN*HH*CC];     // 96 MB
__device__ float g_skip[NN*CC];     // 16 MB
__device__ float g_score[EE*HH];    // 3 MB
__device__ int   g_deg[NN];
__device__ int   g_cnt[NN];
__device__ int   g_off[NN+1];
__device__ int   g_perm[EE];
__device__ float g_m1[GG*CC];
__device__ float g_m2[GG*CC];

// ---------------- CSR build --------------------------------------------------
__global__ void zero_counts(){
    int i = blockIdx.x*blockDim.x + threadIdx.x;
    if(i < NN){ g_deg[i]=0; g_cnt[i]=0; }
}
__global__ void hist_kernel(const int* __restrict__ dst){
    int e = blockIdx.x*blockDim.x + threadIdx.x;
    if(e < EE) atomicAdd(&g_deg[dst[e]], 1);
}
__global__ void scan_kernel(){
    __shared__ int sh[1024];
    __shared__ int sbase;
    int tid = threadIdx.x;
    if(tid==0){ sbase = 0; g_off[0] = 0; }
    __syncthreads();
    for(int chunk=0; chunk<NN/1024; chunk++){
        int idx = chunk*1024 + tid;
        sh[tid] = g_deg[idx];
        __syncthreads();
        for(int o=1;o<1024;o<<=1){
            int t = (tid>=o) ? sh[tid-o] : 0;
            __syncthreads();
            sh[tid] += t;
            __syncthreads();
        }
        g_off[idx+1] = sbase + sh[tid];
        __syncthreads();
        if(tid==1023) sbase += sh[1023];
        __syncthreads();
    }
}
__global__ void scatter_kernel(const int* __restrict__ dst){
    int e = blockIdx.x*blockDim.x + threadIdx.x;
    if(e < EE){
        int d = dst[e];
        int pos = g_off[d] + atomicAdd(&g_cnt[d], 1);
        g_perm[pos] = e;
    }
}

// ---------------- embedding --------------------------------------------------
__global__ void embed_kernel(const int* __restrict__ atoms, const float* __restrict__ embd){
    int i = blockIdx.x*blockDim.x + threadIdx.x;   // over N*C
    int n = i >> 7, c = i & 127;
    g_x[i] = embd[atoms[n]*CC + c];
}

// ---------------- fused QKV+skip projection (fp32 tiled GEMM) ----------------
// out[n][j] = sum_c x[n][c] * W[j][c] + b[j]; 2432 output cols:
// [0,768)=Q, [768,1536)=K, [1536,2304)=V, [2304,2432)=skip.
#define BM 64
#define BN 64
#define BK 32
__global__ __launch_bounds__(256) void gemm_qkvs(
    int parity,
    const float* __restrict__ Wq, const float* __restrict__ bq,
    const float* __restrict__ Wk, const float* __restrict__ bk,
    const float* __restrict__ Wv, const float* __restrict__ bv,
    const float* __restrict__ Ws, const float* __restrict__ bs)
{
    const float* x = parity ? g_xn : g_x;
    int col0 = blockIdx.x * BN;
    const float* W; const float* bias; float* out; int ostr; int colL;
    if(col0 < 768)       { W=Wq; bias=bq; out=g_q;    ostr=HH*CC; colL=col0;      }
    else if(col0 < 1536) { W=Wk; bias=bk; out=g_k;    ostr=HH*CC; colL=col0-768;  }
    else if(col0 < 2304) { W=Wv; bias=bv; out=g_v;    ostr=HH*CC; colL=col0-1536; }
    else                 { W=Ws; bias=bs; out=g_skip; ostr=CC;    colL=col0-2304; }
    int row0 = blockIdx.y * BM;

    __shared__ float sA[BM][BK+1];
    __shared__ float sB[BN][BK+1];
    int tid = threadIdx.x;
    int tx = tid & 15, ty = tid >> 4;
    float acc[4][4];
    #pragma unroll
    for(int i=0;i<4;i++)
        #pragma unroll
        for(int j=0;j<4;j++) acc[i][j]=0.f;

    for(int k0=0; k0<CC; k0+=BK){
        #pragma unroll
        for(int u=0;u<2;u++){
            int li = tid + 256*u;         // 0..511 float4 slots
            int m  = li >> 3;
            int kc = (li & 7) * 4;
            float4 a4 = *(const float4*)&x[(size_t)(row0+m)*CC + k0 + kc];
            sA[m][kc]=a4.x; sA[m][kc+1]=a4.y; sA[m][kc+2]=a4.z; sA[m][kc+3]=a4.w;
            float4 b4 = *(const float4*)&W[(size_t)(colL+m)*CC + k0 + kc];
            sB[m][kc]=b4.x; sB[m][kc+1]=b4.y; sB[m][kc+2]=b4.z; sB[m][kc+3]=b4.w;
        }
        __syncthreads();
        #pragma unroll
        for(int kk=0;kk<BK;kk++){
            float a[4], b[4];
            #pragma unroll
            for(int i=0;i<4;i++) a[i]=sA[ty*4+i][kk];
            #pragma unroll
            for(int j=0;j<4;j++) b[j]=sB[tx*4+j][kk];
            #pragma unroll
            for(int i=0;i<4;i++)
                #pragma unroll
                for(int j=0;j<4;j++)
                    acc[i][j] += a[i]*b[j];
        }
        __syncthreads();
    }
    #pragma unroll
    for(int i=0;i<4;i++){
        int r = row0 + ty*4 + i;
        #pragma unroll
        for(int j=0;j<4;j++){
            int c = colL + tx*4 + j;
            out[(size_t)r*ostr + c] = acc[i][j] + bias[c];
        }
    }
}

// ---------------- attention + residual + LN + ReLU (warp per dst node) -------
__global__ __launch_bounds__(256) void attn_kernel(
    int parity, const int* __restrict__ src,
    const float* __restrict__ lg, const float* __restrict__ lb)
{
    const float* x  = parity ? g_xn : g_x;
    float*       xo = parity ? g_x  : g_xn;
    int warp = (blockIdx.x*blockDim.x + threadIdx.x) >> 5;
    int lane = threadIdx.x & 31;
    if(warp >= NN) return;
    int d = warp;
    const float invsq = 0.08838834764831845f;  // 1/sqrt(128)

    float qv[HH][4];
    #pragma unroll
    for(int h=0;h<HH;h++)
        #pragma unroll
        for(int i=0;i<4;i++)
            qv[h][i] = g_q[(size_t)(d*HH+h)*CC + lane + 32*i];

    int e0 = g_off[d], e1 = g_off[d+1];
    float mx[HH];
    #pragma unroll
    for(int h=0;h<HH;h++) mx[h] = -1e30f;

    // pass 1: scores + per-head max; scores cached to scratch
    for(int t=e0; t<e1; t++){
        int e = g_perm[t];
        int s = src[e];
        float dot[HH];
        #pragma unroll
        for(int h=0;h<HH;h++){
            float dd = 0.f;
            #pragma unroll
            for(int i=0;i<4;i++)
                dd += qv[h][i] * g_k[(size_t)(s*HH+h)*CC + lane + 32*i];
            dot[h] = dd;
        }
        #pragma unroll
        for(int h=0;h<HH;h++){
            #pragma unroll
            for(int o=16;o>0;o>>=1) dot[h] += __shfl_xor_sync(0xffffffffu, dot[h], o);
            dot[h] *= invsq;
            mx[h] = fmaxf(mx[h], dot[h]);
        }
        float myv = dot[0];
        myv = (lane==1)?dot[1]:myv;
        myv = (lane==2)?dot[2]:myv;
        myv = (lane==3)?dot[3]:myv;
        myv = (lane==4)?dot[4]:myv;
        myv = (lane==5)?dot[5]:myv;
        if(lane < HH) g_score[(size_t)t*HH + lane] = myv;
    }
    __syncwarp();

    // pass 2: exp, denominator, weighted V accumulation
    float den[HH];
    float accv[HH][4];
    #pragma unroll
    for(int h=0;h<HH;h++){
        den[h]=0.f;
        #pragma unroll
        for(int i=0;i<4;i++) accv[h][i]=0.f;
    }
    for(int t=e0; t<e1; t++){
        int e = g_perm[t];
        int s = src[e];
        #pragma unroll
        for(int h=0;h<HH;h++){
            float ex = __expf(g_score[(size_t)t*HH + h] - mx[h]);
            den[h] += ex;
            #pragma unroll
            for(int i=0;i<4;i++)
                accv[h][i] += ex * g_v[(size_t)(s*HH+h)*CC + lane + 32*i];
        }
    }

    // head-average + skip + residual
    float outc[4];
    #pragma unroll
    for(int i=0;i<4;i++){
        float a = 0.f;
        #pragma unroll
        for(int h=0;h<HH;h++)
            a += (den[h] > 0.f) ? accv[h][i]/den[h] : 0.f;
        int c = lane + 32*i;
        outc[i] = a*(1.f/HH) + g_skip[(size_t)d*CC + c] + x[(size_t)d*CC + c];
    }

    // layernorm over 128 channels (warp reductions) + ReLU
    float s1 = 0.f;
    #pragma unroll
    for(int i=0;i<4;i++) s1 += outc[i];
    #pragma unroll
    for(int o=16;o>0;o>>=1) s1 += __shfl_xor_sync(0xffffffffu, s1, o);
    float mean = s1 * (1.f/CC);
    float s2 = 0.f;
    #pragma unroll
    for(int i=0;i<4;i++){ float dv = outc[i]-mean; s2 += dv*dv; }
    #pragma unroll
    for(int o=16;o>0;o>>=1) s2 += __shfl_xor_sync(0xffffffffu, s2, o);
    float inv = rsqrtf(s2*(1.f/CC) + 1e-5f);
    #pragma unroll
    for(int i=0;i<4;i++){
        int c = lane + 32*i;
        float y = (outc[i]-mean)*inv*lg[c] + lb[c];
        xo[(size_t)d*CC + c] = fmaxf(y, 0.f);
    }
}

// ---------------- output MLP on supernodes -----------------------------------
__global__ void mlp_kernel(int sel, const float* __restrict__ W, const float* __restrict__ b){
    const float* in  = sel ? g_m1 : g_x;   // supernodes are rows [0, GG)
    float*       out = sel ? g_m2 : g_m1;
    __shared__ float row[CC];
    int g = blockIdx.x, c = threadIdx.x;
    row[c] = in[(size_t)g*CC + c];
    __syncthreads();
    float acc = b[c];
    const float* w = &W[(size_t)c*CC];
    #pragma unroll 8
    for(int k2=0;k2<CC;k2++) acc += row[k2]*w[k2];
    out[(size_t)g*CC + c] = fmaxf(acc, 0.f);
}

__global__ void final_kernel(const float* __restrict__ Wp, const float* __restrict__ bp,
                             float* __restrict__ out){
    int warp = (blockIdx.x*blockDim.x + threadIdx.x) >> 5;
    int lane = threadIdx.x & 31;
    if(warp >= GG) return;
    float a = 0.f;
    #pragma unroll
    for(int i=0;i<4;i++){
        int c = lane + 32*i;
        a += g_m2[(size_t)warp*CC + c] * Wp[c];
    }
    #pragma unroll
    for(int o=16;o>0;o>>=1) a += __shfl_xor_sync(0xffffffffu, a, o);
    if(lane==0) out[warp] = a + bp[0];
}

// ---------------- launch -----------------------------------------------------
extern "C" void kernel_launch(void* const* d_in, const int* in_sizes, int n_in,
                              void* d_out, int out_size)
{
    const int*   atoms = (const int*)d_in[0];
    const int*   ei    = (const int*)d_in[1];
    const int*   src   = ei;
    const int*   dstp  = ei + EE;
    const float* embd  = (const float*)d_in[2];
    const float* Wq    = (const float*)d_in[3];
    const float* bq    = (const float*)d_in[4];
    const float* Wk    = (const float*)d_in[5];
    const float* bk    = (const float*)d_in[6];
    const float* Wv    = (const float*)d_in[7];
    const float* bv    = (const float*)d_in[8];
    const float* Ws    = (const float*)d_in[9];
    const float* bs    = (const float*)d_in[10];
    const float* lg    = (const float*)d_in[11];
    const float* lb    = (const float*)d_in[12];
    const float* Wlin  = (const float*)d_in[13];
    const float* blin  = (const float*)d_in[14];
    const float* Wp    = (const float*)d_in[15];
    const float* bp    = (const float*)d_in[16];
    float* out = (float*)d_out;

    zero_counts<<<(NN+255)/256, 256>>>();
    hist_kernel<<<EE/256, 256>>>(dstp);
    scan_kernel<<<1, 1024>>>();
    scatter_kernel<<<EE/256, 256>>>(dstp);
    embed_kernel<<<NN*CC/256, 256>>>(atoms, embd);

    for(int l=0; l<LL; l++){
        int parity = l & 1;
        dim3 grid(2432/BN, NN/BM);
        gemm_qkvs<<<grid, 256>>>(parity,
            Wq + (size_t)l*HH*CC*CC, bq + (size_t)l*HH*CC,
            Wk + (size_t)l*HH*CC*CC, bk + (size_t)l*HH*CC,
            Wv + (size_t)l*HH*CC*CC, bv + (size_t)l*HH*CC,
            Ws + (size_t)l*CC*CC,    bs + (size_t)l*CC);
        attn_kernel<<<NN/8, 256>>>(parity, src, lg + (size_t)l*CC, lb + (size_t)l*CC);
    }

    mlp_kernel<<<GG, CC>>>(0, Wlin,          blin);
    mlp_kernel<<<GG, CC>>>(1, Wlin + CC*CC,  blin + CC);
    final_kernel<<<GG*32/256, 256>>>(Wp, bp, out);
}

// round 2
// speedup vs baseline: 1.4411x; 1.4411x over previous
#include <cuda_runtime.h>
#include <cuda_bf16.h>
#include <math.h>

#define NN 32768
#define EE 131072
#define HH 6
#define CC 128
#define LL 6
#define GG 2048
#define NCOL 2432   // 768 q + 768 k + 768 v + 128 skip

// ---------------- scratch (device globals; no allocation allowed) ------------
__device__ float g_x[NN*CC];
__device__ float g_xn[NN*CC];
__device__ __nv_bfloat16 g_xh[NN*CC];
__device__ __nv_bfloat16 g_xl[NN*CC];
__device__ float g_q[NN*HH*CC];
__device__ float g_k[NN*HH*CC];
__device__ float g_v[NN*HH*CC];
__device__ float g_skip[NN*CC];
__device__ float g_score[EE*HH];
__device__ __nv_bfloat16 g_Wh[LL*NCOL*CC];
__device__ __nv_bfloat16 g_Wl[LL*NCOL*CC];
__device__ float g_bias[LL*NCOL];
__device__ int   g_deg[NN];
__device__ int   g_cnt[NN];
__device__ int   g_off[NN+1];
__device__ int   g_perm[EE];
__device__ float g_m1[GG*CC];
__device__ float g_m2[GG*CC];

// ---------------- prep: weight bf16-split conversion + counter zeroing -------
__global__ void prep_kernel(
    const float* __restrict__ Wq, const float* __restrict__ Wk,
    const float* __restrict__ Wv, const float* __restrict__ Ws,
    const float* __restrict__ bq, const float* __restrict__ bk,
    const float* __restrict__ bv, const float* __restrict__ bs)
{
    int idx = blockIdx.x*blockDim.x + threadIdx.x;
    if(idx < NN){ g_deg[idx]=0; g_cnt[idx]=0; }
    if(idx < LL*NCOL){
        int l = idx / NCOL, r = idx % NCOL;
        float b;
        if(r<768)       b = bq[l*768 + r];
        else if(r<1536) b = bk[l*768 + r-768];
        else if(r<2304) b = bv[l*768 + r-1536];
        else            b = bs[l*128 + r-2304];
        g_bias[idx] = b;
    }
    if(idx < LL*NCOL*CC){
        int l = idx / (NCOL*CC);
        int r = (idx / CC) % NCOL;
        int c = idx % CC;
        float v;
        if(r<768)       v = Wq[((size_t)l*768 + r)*CC + c];
        else if(r<1536) v = Wk[((size_t)l*768 + r-768)*CC + c];
        else if(r<2304) v = Wv[((size_t)l*768 + r-1536)*CC + c];
        else            v = Ws[((size_t)l*128 + r-2304)*CC + c];
        __nv_bfloat16 h = __float2bfloat16(v);
        g_Wh[idx] = h;
        g_Wl[idx] = __float2bfloat16(v - __bfloat162float(h));
    }
}

// ---------------- CSR build --------------------------------------------------
__global__ void hist_kernel(const int* __restrict__ dst){
    int e = blockIdx.x*blockDim.x + threadIdx.x;
    if(e < EE) atomicAdd(&g_deg[dst[e]], 1);
}
__global__ void scan_kernel(){
    __shared__ int sh[1024];
    __shared__ int sbase;
    int tid = threadIdx.x;
    if(tid==0){ sbase = 0; g_off[0] = 0; }
    __syncthreads();
    for(int chunk=0; chunk<NN/1024; chunk++){
        int idx = chunk*1024 + tid;
        sh[tid] = g_deg[idx];
        __syncthreads();
        for(int o=1;o<1024;o<<=1){
            int t = (tid>=o) ? sh[tid-o] : 0;
            __syncthreads();
            sh[tid] += t;
            __syncthreads();
        }
        g_off[idx+1] = sbase + sh[tid];
        __syncthreads();
        if(tid==1023) sbase += sh[1023];
        __syncthreads();
    }
}
__global__ void scatter_kernel(const int* __restrict__ dst){
    int e = blockIdx.x*blockDim.x + threadIdx.x;
    if(e < EE){
        int d = dst[e];
        int pos = g_off[d] + atomicAdd(&g_cnt[d], 1);
        g_perm[pos] = e;
    }
}

// ---------------- embedding (+ bf16 split) -----------------------------------
__global__ void embed_kernel(const int* __restrict__ atoms, const float* __restrict__ embd){
    int i = blockIdx.x*blockDim.x + threadIdx.x;   // over N*C
    int n = i >> 7, c = i & 127;
    float v = embd[atoms[n]*CC + c];
    g_x[i] = v;
    __nv_bfloat16 h = __float2bfloat16(v);
    g_xh[i] = h;
    g_xl[i] = __float2bfloat16(v - __bfloat162float(h));
}

// ---------------- fused QKV+skip projection (bf16-split tensor-core GEMM) ----
// out[n][j] = sum_c x[n][c] * W[j][c] + b[j]; cols: [0,768)=Q, [768,1536)=K,
// [1536,2304)=V, [2304,2432)=skip. x,W split into bf16 hi+lo; 3 MMAs recover
// ~fp32 accuracy (drops only lo*lo ~ 2^-16 relative).
#define MMA16816(d, a, b) asm volatile( \
    "mma.sync.aligned.m16n8k16.row.col.f32.bf16.bf16.f32 " \
    "{%0,%1,%2,%3}, {%4,%5,%6,%7}, {%8,%9}, {%0,%1,%2,%3};" \
    : "+f"(d[0]),"+f"(d[1]),"+f"(d[2]),"+f"(d[3]) \
    : "r"(a[0]),"r"(a[1]),"r"(a[2]),"r"(a[3]), "r"(b[0]),"r"(b[1]))

__global__ __launch_bounds__(256) void gemm_mma(int layer)
{
    __shared__ __nv_bfloat16 sAh[64][72], sAl[64][72], sBh[64][72], sBl[64][72];
    int col0 = blockIdx.x * 64;
    int row0 = blockIdx.y * 64;

    float* out; int ostr; int colL;
    if(col0 < 768)       { out=g_q;    ostr=HH*CC; colL=col0;      }
    else if(col0 < 1536) { out=g_k;    ostr=HH*CC; colL=col0-768;  }
    else if(col0 < 2304) { out=g_v;    ostr=HH*CC; colL=col0-1536; }
    else                 { out=g_skip; ostr=CC;    colL=col0-2304; }

    int tid  = threadIdx.x;
    int warp = tid >> 5, lane = tid & 31;
    int wm = warp >> 2, wn = warp & 3;         // 2 x 4 warp grid
    int gid = lane >> 2, tig = lane & 3;
    int wr0 = wm * 32, wc0 = wn * 16;

    float acc[2][2][4];
    #pragma unroll
    for(int i=0;i<2;i++)
        #pragma unroll
        for(int j=0;j<2;j++)
            #pragma unroll
            for(int t=0;t<4;t++) acc[i][j][t] = 0.f;

    int lr = tid >> 2;            // 0..63 : tile row loaded by this thread
    int lc = (tid & 3) * 16;      // 0,16,32,48 : 16 bf16 (= 2 uint4) per thread
    const __nv_bfloat16* Ah = &g_xh[(size_t)(row0+lr)*CC + lc];
    const __nv_bfloat16* Al = &g_xl[(size_t)(row0+lr)*CC + lc];
    size_t wb = ((size_t)layer*NCOL + col0 + lr)*CC + lc;
    const __nv_bfloat16* Bh = &g_Wh[wb];
    const __nv_bfloat16* Bl = &g_Wl[wb];

    #pragma unroll
    for(int kit=0; kit<2; kit++){
        int k0 = kit * 64;
        *(uint4*)&sAh[lr][lc]   = *(const uint4*)(Ah + k0);
        *(uint4*)&sAh[lr][lc+8] = *(const uint4*)(Ah + k0 + 8);
        *(uint4*)&sAl[lr][lc]   = *(const uint4*)(Al + k0);
        *(uint4*)&sAl[lr][lc+8] = *(const uint4*)(Al + k0 + 8);
        *(uint4*)&sBh[lr][lc]   = *(const uint4*)(Bh + k0);
        *(uint4*)&sBh[lr][lc+8] = *(const uint4*)(Bh + k0 + 8);
        *(uint4*)&sBl[lr][lc]   = *(const uint4*)(Bl + k0);
        *(uint4*)&sBl[lr][lc+8] = *(const uint4*)(Bl + k0 + 8);
        __syncthreads();

        #pragma unroll
        for(int ks=0; ks<64; ks+=16){
            unsigned ah[2][4], al[2][4], bh[2][2], bl[2][2];
            #pragma unroll
            for(int i=0;i<2;i++){
                int r = wr0 + i*16 + gid;
                ah[i][0] = *(const unsigned*)&sAh[r  ][ks   + 2*tig];
                ah[i][1] = *(const unsigned*)&sAh[r+8][ks   + 2*tig];
                ah[i][2] = *(const unsigned*)&sAh[r  ][ks+8 + 2*tig];
                ah[i][3] = *(const unsigned*)&sAh[r+8][ks+8 + 2*tig];
                al[i][0] = *(const unsigned*)&sAl[r  ][ks   + 2*tig];
                al[i][1] = *(const unsigned*)&sAl[r+8][ks   + 2*tig];
                al[i][2] = *(const unsigned*)&sAl[r  ][ks+8 + 2*tig];
                al[i][3] = *(const unsigned*)&sAl[r+8][ks+8 + 2*tig];
            }
            #pragma unroll
            for(int j=0;j<2;j++){
                int c = wc0 + j*8 + gid;
                bh[j][0] = *(const unsigned*)&sBh[c][ks   + 2*tig];
                bh[j][1] = *(const unsigned*)&sBh[c][ks+8 + 2*tig];
                bl[j][0] = *(const unsigned*)&sBl[c][ks   + 2*tig];
                bl[j][1] = *(const unsigned*)&sBl[c][ks+8 + 2*tig];
            }
            #pragma unroll
            for(int i=0;i<2;i++)
                #pragma unroll
                for(int j=0;j<2;j++){
                    MMA16816(acc[i][j], ah[i], bh[j]);
                    MMA16816(acc[i][j], ah[i], bl[j]);
                    MMA16816(acc[i][j], al[i], bh[j]);
                }
        }
        __syncthreads();
    }

    #pragma unroll
    for(int i=0;i<2;i++){
        int r = row0 + wr0 + i*16 + gid;
        #pragma unroll
        for(int j=0;j<2;j++){
            int c  = colL + wc0 + j*8 + 2*tig;
            int cb = layer*NCOL + col0 + wc0 + j*8 + 2*tig;
            float b0 = g_bias[cb], b1 = g_bias[cb+1];
            out[(size_t)r*ostr + c]       = acc[i][j][0] + b0;
            out[(size_t)r*ostr + c + 1]   = acc[i][j][1] + b1;
            out[(size_t)(r+8)*ostr + c]   = acc[i][j][2] + b0;
            out[(size_t)(r+8)*ostr + c+1] = acc[i][j][3] + b1;
        }
    }
}

// ---------------- attention + residual + LN + ReLU (warp per dst node) -------
__global__ __launch_bounds__(256) void attn_kernel(
    int parity, const int* __restrict__ src,
    const float* __restrict__ lg, const float* __restrict__ lb)
{
    const float* x  = parity ? g_xn : g_x;
    float*       xo = parity ? g_x  : g_xn;
    int warp = (blockIdx.x*blockDim.x + threadIdx.x) >> 5;
    int lane = threadIdx.x & 31;
    if(warp >= NN) return;
    int d = warp;
    const float invsq = 0.08838834764831845f;  // 1/sqrt(128)

    float qv[HH][4];
    #pragma unroll
    for(int h=0;h<HH;h++)
        #pragma unroll
        for(int i=0;i<4;i++)
            qv[h][i] = g_q[(size_t)(d*HH+h)*CC + lane + 32*i];

    int e0 = g_off[d], e1 = g_off[d+1];
    float mx[HH];
    #pragma unroll
    for(int h=0;h<HH;h++) mx[h] = -1e30f;

    // pass 1: scores + per-head max; scores cached to scratch
    for(int t=e0; t<e1; t++){
        int e = g_perm[t];
        int s = src[e];
        float dot[HH];
        #pragma unroll
        for(int h=0;h<HH;h++){
            float dd = 0.f;
            #pragma unroll
            for(int i=0;i<4;i++)
                dd += qv[h][i] * g_k[(size_t)(s*HH+h)*CC + lane + 32*i];
            dot[h] = dd;
        }
        #pragma unroll
        for(int h=0;h<HH;h++){
            #pragma unroll
            for(int o=16;o>0;o>>=1) dot[h] += __shfl_xor_sync(0xffffffffu, dot[h], o);
            dot[h] *= invsq;
            mx[h] = fmaxf(mx[h], dot[h]);
        }
        float myv = dot[0];
        myv = (lane==1)?dot[1]:myv;
        myv = (lane==2)?dot[2]:myv;
        myv = (lane==3)?dot[3]:myv;
        myv = (lane==4)?dot[4]:myv;
        myv = (lane==5)?dot[5]:myv;
        if(lane < HH) g_score[(size_t)t*HH + lane] = myv;
    }
    __syncwarp();

    // pass 2: exp, denominator, weighted V accumulation
    float den[HH];
    float accv[HH][4];
    #pragma unroll
    for(int h=0;h<HH;h++){
        den[h]=0.f;
        #pragma unroll
        for(int i=0;i<4;i++) accv[h][i]=0.f;
    }
    for(int t=e0; t<e1; t++){
        int e = g_perm[t];
        int s = src[e];
        #pragma unroll
        for(int h=0;h<HH;h++){
            float ex = __expf(g_score[(size_t)t*HH + h] - mx[h]);
            den[h] += ex;
            #pragma unroll
            for(int i=0;i<4;i++)
                accv[h][i] += ex * g_v[(size_t)(s*HH+h)*CC + lane + 32*i];
        }
    }

    // head-average + skip + residual
    float outc[4];
    #pragma unroll
    for(int i=0;i<4;i++){
        float a = 0.f;
        #pragma unroll
        for(int h=0;h<HH;h++)
            a += (den[h] > 0.f) ? accv[h][i]/den[h] : 0.f;
        int c = lane + 32*i;
        outc[i] = a*(1.f/HH) + g_skip[(size_t)d*CC + c] + x[(size_t)d*CC + c];
    }

    // layernorm over 128 channels (warp reductions) + ReLU
    float s1 = 0.f;
    #pragma unroll
    for(int i=0;i<4;i++) s1 += outc[i];
    #pragma unroll
    for(int o=16;o>0;o>>=1) s1 += __shfl_xor_sync(0xffffffffu, s1, o);
    float mean = s1 * (1.f/CC);
    float s2 = 0.f;
    #pragma unroll
    for(int i=0;i<4;i++){ float dv = outc[i]-mean; s2 += dv*dv; }
    #pragma unroll
    for(int o=16;o>0;o>>=1) s2 += __shfl_xor_sync(0xffffffffu, s2, o);
    float inv = rsqrtf(s2*(1.f/CC) + 1e-5f);
    #pragma unroll
    for(int i=0;i<4;i++){
        int c = lane + 32*i;
        float y = (outc[i]-mean)*inv*lg[c] + lb[c];
        y = fmaxf(y, 0.f);
        xo[(size_t)d*CC + c] = y;
        __nv_bfloat16 h16 = __float2bfloat16(y);
        g_xh[(size_t)d*CC + c] = h16;
        g_xl[(size_t)d*CC + c] = __float2bfloat16(y - __bfloat162float(h16));
    }
}

// ---------------- output MLP on supernodes -----------------------------------
__global__ void mlp_kernel(int sel, const float* __restrict__ W, const float* __restrict__ b){
    const float* in  = sel ? g_m1 : g_x;   // supernodes are rows [0, GG)
    float*       out = sel ? g_m2 : g_m1;
    __shared__ float row[CC];
    int g = blockIdx.x, c = threadIdx.x;
    row[c] = in[(size_t)g*CC + c];
    __syncthreads();
    float acc = b[c];
    const float* w = &W[(size_t)c*CC];
    #pragma unroll 8
    for(int k2=0;k2<CC;k2++) acc += row[k2]*w[k2];
    out[(size_t)g*CC + c] = fmaxf(acc, 0.f);
}

__global__ void final_kernel(const float* __restrict__ Wp, const float* __restrict__ bp,
                             float* __restrict__ out){
    int warp = (blockIdx.x*blockDim.x + threadIdx.x) >> 5;
    int lane = threadIdx.x & 31;
    if(warp >= GG) return;
    float a = 0.f;
    #pragma unroll
    for(int i=0;i<4;i++){
        int c = lane + 32*i;
        a += g_m2[(size_t)warp*CC + c] * Wp[c];
    }
    #pragma unroll
    for(int o=16;o>0;o>>=1) a += __shfl_xor_sync(0xffffffffu, a, o);
    if(lane==0) out[warp] = a + bp[0];
}

// ---------------- launch -----------------------------------------------------
extern "C" void kernel_launch(void* const* d_in, const int* in_sizes, int n_in,
                              void* d_out, int out_size)
{
    const int*   atoms = (const int*)d_in[0];
    const int*   ei    = (const int*)d_in[1];
    const int*   src   = ei;
    const int*   dstp  = ei + EE;
    const float* embd  = (const float*)d_in[2];
    const float* Wq    = (const float*)d_in[3];
    const float* bq    = (const float*)d_in[4];
    const float* Wk    = (const float*)d_in[5];
    const float* bk    = (const float*)d_in[6];
    const float* Wv    = (const float*)d_in[7];
    const float* bv    = (const float*)d_in[8];
    const float* Ws    = (const float*)d_in[9];
    const float* bs    = (const float*)d_in[10];
    const float* lg    = (const float*)d_in[11];
    const float* lb    = (const float*)d_in[12];
    const float* Wlin  = (const float*)d_in[13];
    const float* blin  = (const float*)d_in[14];
    const float* Wp    = (const float*)d_in[15];
    const float* bp    = (const float*)d_in[16];
    float* out = (float*)d_out;

    // launch order chosen so ncu (-s 5 -c 1) captures gemm_mma (6th launch)
    prep_kernel<<<(LL*NCOL*CC + 255)/256, 256>>>(Wq,Wk,Wv,Ws,bq,bk,bv,bs);   // 1
    hist_kernel<<<EE/256, 256>>>(dstp);                                       // 2
    scan_kernel<<<1, 1024>>>();                                               // 3
    scatter_kernel<<<EE/256, 256>>>(dstp);                                    // 4
    embed_kernel<<<NN*CC/256, 256>>>(atoms, embd);                            // 5

    for(int l=0; l<LL; l++){
        int parity = l & 1;
        dim3 grid(NCOL/64, NN/64);
        gemm_mma<<<grid, 256>>>(l);                                           // 6 (l=0)
        attn_kernel<<<NN/8, 256>>>(parity, src, lg + (size_t)l*CC, lb + (size_t)l*CC);
    }

    mlp_kernel<<<GG, CC>>>(0, Wlin,          blin);
    mlp_kernel<<<GG, CC>>>(1, Wlin + CC*CC,  blin + CC);
    final_kernel<<<GG*32/256, 256>>>(Wp, bp, out);
}

// round 3
// speedup vs baseline: 1.9960x; 1.3851x over previous
#include <cuda_runtime.h>
#include <cuda_bf16.h>
#include <math.h>

#define NN 32768
#define EE 131072
#define HH 6
#define CC 128
#define LL 6
#define GG 2048
#define PC 768      // p / y width (H*C)
#define KB 896      // gemm B K dim (768 y + 128 x)

// ---------------- scratch (device globals) -----------------------------------
__device__ float g_x[NN*CC];
__device__ float g_xn[NN*CC];
__device__ __nv_bfloat16 g_xh[NN*CC];
__device__ __nv_bfloat16 g_xl[NN*CC];
__device__ float g_p[NN*PC];
__device__ __nv_bfloat16 g_yh[NN*PC];
__device__ __nv_bfloat16 g_yl[NN*PC];
__device__ float g_score[EE*HH];
__device__ __nv_bfloat16 g_WAh[LL*PC*CC];   // Wqk = Wk^T Wq per head, bf16 hi
__device__ __nv_bfloat16 g_WAl[LL*PC*CC];   // lo
__device__ float g_bqk[LL*PC];
__device__ __nv_bfloat16 g_WBh[LL*CC*KB];   // [Wv/H | Ws^T] combined, bf16 hi
__device__ __nv_bfloat16 g_WBl[LL*CC*KB];
__device__ float g_bvm[LL*CC];              // mean_h bv
__device__ int   g_deg[NN];
__device__ int   g_cnt[NN];
__device__ int   g_off[NN+1];
__device__ int   g_perm[EE];
__device__ float g_m1[GG*CC];
__device__ float g_m2[GG*CC];

// ---------------- prep: fold weights + zero counters (single launch) ---------
// blocks [0,4608): Wqk_h[c,c2] = sum_cc Wk[h*128+cc,c]*Wq[h*128+cc,c2]
// blocks [4608,4644): bqk
// blocks [4644,10020): WB fill
// blocks [10020,10276): zero deg/cnt
// blocks [10276,10282): bvm
__global__ void prep_kernel(
    const float* __restrict__ Wq, const float* __restrict__ Wk,
    const float* __restrict__ Wv, const float* __restrict__ Ws,
    const float* __restrict__ bq, const float* __restrict__ bv)
{
    int bid = blockIdx.x, tid = threadIdx.x;
    if(bid < 4608){
        int l = bid / (HH*CC);
        int rem = bid % (HH*CC);
        int h = rem >> 7, c = rem & 127;
        __shared__ float wk[128];
        wk[tid] = Wk[((size_t)l*PC + h*CC + tid)*CC + c];
        __syncthreads();
        float acc = 0.f;
        const float* wqp = &Wq[((size_t)l*PC + h*CC)*CC + tid];
        #pragma unroll 8
        for(int cc=0; cc<CC; cc++) acc += wk[cc] * wqp[(size_t)cc*CC];
        size_t o = ((size_t)l*PC + h*CC + c)*CC + tid;
        __nv_bfloat16 hi = __float2bfloat16(acc);
        g_WAh[o] = hi;
        g_WAl[o] = __float2bfloat16(acc - __bfloat162float(hi));
    } else if(bid < 4644){
        int b2 = bid - 4608;
        int l = b2 / HH, h = b2 % HH;
        float acc = 0.f;
        for(int cc=0; cc<CC; cc++)
            acc += bq[l*PC + h*CC + cc] * Wk[((size_t)l*PC + h*CC + cc)*CC + tid];
        g_bqk[l*PC + h*CC + tid] = acc;
    } else if(bid < 10020){
        int idx = (bid-4644)*128 + tid;          // over LL*CC*KB
        int l = idx / (CC*KB);
        int j = (idx / KB) % CC;
        int c = idx % KB;
        float v;
        if(c < PC){
            int h = c >> 7, cp = c & 127;
            v = Wv[((size_t)l*PC + h*CC + j)*CC + cp] * (1.f/HH);
        } else {
            v = Ws[((size_t)l*CC + j)*CC + (c - PC)];
        }
        size_t o = ((size_t)l*CC + j)*KB + c;
        __nv_bfloat16 hi = __float2bfloat16(v);
        g_WBh[o] = hi;
        g_WBl[o] = __float2bfloat16(v - __bfloat162float(hi));
    } else if(bid < 10276){
        int i = (bid-10020)*128 + tid;
        g_deg[i]=0; g_cnt[i]=0;
    } else {
        int i = (bid-10276)*128 + tid;           // LL*CC
        int l = i >> 7, j = i & 127;
        float a = 0.f;
        #pragma unroll
        for(int h=0;h<HH;h++) a += bv[l*PC + h*CC + j];
        g_bvm[i] = a * (1.f/HH);
    }
}

// ---------------- CSR build --------------------------------------------------
__global__ void hist_kernel(const int* __restrict__ dst){
    int e = blockIdx.x*blockDim.x + threadIdx.x;
    if(e < EE) atomicAdd(&g_deg[dst[e]], 1);
}
__global__ void scan_kernel(){
    __shared__ int sh[1024];
    __shared__ int sbase;
    int tid = threadIdx.x;
    if(tid==0){ sbase = 0; g_off[0] = 0; }
    __syncthreads();
    for(int chunk=0; chunk<NN/1024; chunk++){
        int idx = chunk*1024 + tid;
        sh[tid] = g_deg[idx];
        __syncthreads();
        for(int o=1;o<1024;o<<=1){
            int t = (tid>=o) ? sh[tid-o] : 0;
            __syncthreads();
            sh[tid] += t;
            __syncthreads();
        }
        g_off[idx+1] = sbase + sh[tid];
        __syncthreads();
        if(tid==1023) sbase += sh[1023];
        __syncthreads();
    }
}
__global__ void scatter_kernel(const int* __restrict__ dst){
    int e = blockIdx.x*blockDim.x + threadIdx.x;
    if(e < EE){
        int d = dst[e];
        int pos = g_off[d] + atomicAdd(&g_cnt[d], 1);
        g_perm[pos] = e;
    }
}

// ---------------- embedding (+ bf16 split) -----------------------------------
__global__ void embed_kernel(const int* __restrict__ atoms, const float* __restrict__ embd){
    int i = blockIdx.x*blockDim.x + threadIdx.x;
    int n = i >> 7, c = i & 127;
    float v = embd[atoms[n]*CC + c];
    g_x[i] = v;
    __nv_bfloat16 h = __float2bfloat16(v);
    g_xh[i] = h;
    g_xl[i] = __float2bfloat16(v - __bfloat162float(h));
}

// ---------------- MMA macro (bf16-split, fp32 accum) -------------------------
#define MMA16816(d, a, b) asm volatile( \
    "mma.sync.aligned.m16n8k16.row.col.f32.bf16.bf16.f32 " \
    "{%0,%1,%2,%3}, {%4,%5,%6,%7}, {%8,%9}, {%0,%1,%2,%3};" \
    : "+f"(d[0]),"+f"(d[1]),"+f"(d[2]),"+f"(d[3]) \
    : "r"(a[0]),"r"(a[1]),"r"(a[2]),"r"(a[3]), "r"(b[0]),"r"(b[1]))

// ---------------- GEMM A: p = x @ Wqk^T + bqk  [N,768] -----------------------
__global__ __launch_bounds__(256) void gemm_p(int layer)
{
    __shared__ __nv_bfloat16 sAh[64][72], sAl[64][72], sBh[64][72], sBl[64][72];
    int col0 = blockIdx.x * 64;
    int row0 = blockIdx.y * 64;

    int tid  = threadIdx.x;
    int warp = tid >> 5, lane = tid & 31;
    int wm = warp >> 2, wn = warp & 3;
    int gid = lane >> 2, tig = lane & 3;
    int wr0 = wm * 32, wc0 = wn * 16;

    float acc[2][2][4];
    #pragma unroll
    for(int i=0;i<2;i++)
        #pragma unroll
        for(int j=0;j<2;j++)
            #pragma unroll
            for(int t=0;t<4;t++) acc[i][j][t] = 0.f;

    int lr = tid >> 2;
    int lc = (tid & 3) * 16;
    const __nv_bfloat16* Ah = &g_xh[(size_t)(row0+lr)*CC + lc];
    const __nv_bfloat16* Al = &g_xl[(size_t)(row0+lr)*CC + lc];
    size_t wb = ((size_t)layer*PC + col0 + lr)*CC + lc;
    const __nv_bfloat16* Bh = &g_WAh[wb];
    const __nv_bfloat16* Bl = &g_WAl[wb];

    #pragma unroll
    for(int kit=0; kit<2; kit++){
        int k0 = kit * 64;
        *(uint4*)&sAh[lr][lc]   = *(const uint4*)(Ah + k0);
        *(uint4*)&sAh[lr][lc+8] = *(const uint4*)(Ah + k0 + 8);
        *(uint4*)&sAl[lr][lc]   = *(const uint4*)(Al + k0);
        *(uint4*)&sAl[lr][lc+8] = *(const uint4*)(Al + k0 + 8);
        *(uint4*)&sBh[lr][lc]   = *(const uint4*)(Bh + k0);
        *(uint4*)&sBh[lr][lc+8] = *(const uint4*)(Bh + k0 + 8);
        *(uint4*)&sBl[lr][lc]   = *(const uint4*)(Bl + k0);
        *(uint4*)&sBl[lr][lc+8] = *(const uint4*)(Bl + k0 + 8);
        __syncthreads();

        #pragma unroll
        for(int ks=0; ks<64; ks+=16){
            unsigned ah[2][4], al[2][4], bh[2][2], bl[2][2];
            #pragma unroll
            for(int i=0;i<2;i++){
                int r = wr0 + i*16 + gid;
                ah[i][0] = *(const unsigned*)&sAh[r  ][ks   + 2*tig];
                ah[i][1] = *(const unsigned*)&sAh[r+8][ks   + 2*tig];
                ah[i][2] = *(const unsigned*)&sAh[r  ][ks+8 + 2*tig];
                ah[i][3] = *(const unsigned*)&sAh[r+8][ks+8 + 2*tig];
                al[i][0] = *(const unsigned*)&sAl[r  ][ks   + 2*tig];
                al[i][1] = *(const unsigned*)&sAl[r+8][ks   + 2*tig];
                al[i][2] = *(const unsigned*)&sAl[r  ][ks+8 + 2*tig];
                al[i][3] = *(const unsigned*)&sAl[r+8][ks+8 + 2*tig];
            }
            #pragma unroll
            for(int j=0;j<2;j++){
                int c = wc0 + j*8 + gid;
                bh[j][0] = *(const unsigned*)&sBh[c][ks   + 2*tig];
                bh[j][1] = *(const unsigned*)&sBh[c][ks+8 + 2*tig];
                bl[j][0] = *(const unsigned*)&sBl[c][ks   + 2*tig];
                bl[j][1] = *(const unsigned*)&sBl[c][ks+8 + 2*tig];
            }
            #pragma unroll
            for(int i=0;i<2;i++)
                #pragma unroll
                for(int j=0;j<2;j++){
                    MMA16816(acc[i][j], ah[i], bh[j]);
                    MMA16816(acc[i][j], ah[i], bl[j]);
                    MMA16816(acc[i][j], al[i], bh[j]);
                }
        }
        __syncthreads();
    }

    #pragma unroll
    for(int i=0;i<2;i++){
        int r = row0 + wr0 + i*16 + gid;
        #pragma unroll
        for(int j=0;j<2;j++){
            int c = col0 + wc0 + j*8 + 2*tig;
            float b0 = g_bqk[layer*PC + c], b1 = g_bqk[layer*PC + c + 1];
            g_p[(size_t)r*PC + c]       = acc[i][j][0] + b0;
            g_p[(size_t)r*PC + c + 1]   = acc[i][j][1] + b1;
            g_p[(size_t)(r+8)*PC + c]   = acc[i][j][2] + b0;
            g_p[(size_t)(r+8)*PC + c+1] = acc[i][j][3] + b1;
        }
    }
}

// ---------------- attention: softmax over edges, aggregate x -----------------
__global__ __launch_bounds__(256) void attn_kernel(int parity, const int* __restrict__ src)
{
    const float4* x4 = (const float4*)(parity ? g_xn : g_x);
    int warp = (blockIdx.x*blockDim.x + threadIdx.x) >> 5;
    int lane = threadIdx.x & 31;
    if(warp >= NN) return;
    int d = warp;
    const float invsq = 0.08838834764831845f;  // 1/sqrt(128)

    const float4* p4 = (const float4*)g_p;
    float4 p[HH];
    #pragma unroll
    for(int h=0;h<HH;h++) p[h] = p4[(size_t)d*192 + h*32 + lane];

    int e0 = g_off[d], e1 = g_off[d+1];
    float mx[HH];
    #pragma unroll
    for(int h=0;h<HH;h++) mx[h] = -1e30f;

    // pass 1: scores (p[dst] . x[src]) + per-head max; cache scores
    for(int t=e0; t<e1; t++){
        int s = src[g_perm[t]];
        float4 xv = x4[(size_t)s*32 + lane];
        float dot[HH];
        #pragma unroll
        for(int h=0;h<HH;h++)
            dot[h] = p[h].x*xv.x + p[h].y*xv.y + p[h].z*xv.z + p[h].w*xv.w;
        #pragma unroll
        for(int h=0;h<HH;h++){
            #pragma unroll
            for(int o=16;o>0;o>>=1) dot[h] += __shfl_xor_sync(0xffffffffu, dot[h], o);
            dot[h] *= invsq;
            mx[h] = fmaxf(mx[h], dot[h]);
        }
        float myv = dot[0];
        myv = (lane==1)?dot[1]:myv;
        myv = (lane==2)?dot[2]:myv;
        myv = (lane==3)?dot[3]:myv;
        myv = (lane==4)?dot[4]:myv;
        myv = (lane==5)?dot[5]:myv;
        if(lane < HH) g_score[(size_t)t*HH + lane] = myv;
    }
    __syncwarp();

    // pass 2: exp, denominator, weighted x accumulation
    float den[HH];
    float4 y[HH];
    #pragma unroll
    for(int h=0;h<HH;h++){ den[h]=0.f; y[h]=make_float4(0.f,0.f,0.f,0.f); }
    for(int t=e0; t<e1; t++){
        int s = src[g_perm[t]];
        float4 xv = x4[(size_t)s*32 + lane];
        #pragma unroll
        for(int h=0;h<HH;h++){
            float ex = __expf(g_score[(size_t)t*HH + h] - mx[h]);
            den[h] += ex;
            y[h].x += ex*xv.x; y[h].y += ex*xv.y;
            y[h].z += ex*xv.z; y[h].w += ex*xv.w;
        }
    }

    // normalize, bf16-split store y
    size_t base = (size_t)d*PC;
    #pragma unroll
    for(int h=0;h<HH;h++){
        float r = (den[h] > 0.f) ? 1.f/den[h] : 0.f;
        float v0=y[h].x*r, v1=y[h].y*r, v2=y[h].z*r, v3=y[h].w*r;
        int c = h*CC + lane*4;
        __nv_bfloat16 h0=__float2bfloat16(v0), h1=__float2bfloat16(v1);
        __nv_bfloat16 h2=__float2bfloat16(v2), h3=__float2bfloat16(v3);
        *(__nv_bfloat162*)&g_yh[base+c]   = __nv_bfloat162(h0, h1);
        *(__nv_bfloat162*)&g_yh[base+c+2] = __nv_bfloat162(h2, h3);
        __nv_bfloat16 l0=__float2bfloat16(v0-__bfloat162float(h0));
        __nv_bfloat16 l1=__float2bfloat16(v1-__bfloat162float(h1));
        __nv_bfloat16 l2=__float2bfloat16(v2-__bfloat162float(h2));
        __nv_bfloat16 l3=__float2bfloat16(v3-__bfloat162float(h3));
        *(__nv_bfloat162*)&g_yl[base+c]   = __nv_bfloat162(l0, l1);
        *(__nv_bfloat162*)&g_yl[base+c+2] = __nv_bfloat162(l2, l3);
    }
}

// ---------------- GEMM B: out = [y|x] @ WB^T (+bias,+res) -> LN -> ReLU ------
__global__ __launch_bounds__(256) void gemm_b(
    int layer, int parity,
    const float* __restrict__ bs, const float* __restrict__ lg, const float* __restrict__ lb)
{
    const float* xold = parity ? g_xn : g_x;
    float*       xo   = parity ? g_x  : g_xn;
    __shared__ union {
        struct {
            __nv_bfloat16 Ah[64][40], Al[64][40];
            __nv_bfloat16 Bh[128][40], Bl[128][40];
        } mm;
        float C[64][132];
    } sm;
    int row0 = blockIdx.x * 64;
    int tid = threadIdx.x, warp = tid >> 5, lane = tid & 31;
    int wm = warp >> 2, wn = warp & 3;
    int gid = lane >> 2, tig = lane & 3;
    int wr0 = wm * 32, wc0 = wn * 32;

    float acc[2][4][4];
    #pragma unroll
    for(int i=0;i<2;i++)
        #pragma unroll
        for(int j=0;j<4;j++)
            #pragma unroll
            for(int t=0;t<4;t++) acc[i][j][t] = 0.f;

    int lr = tid >> 2, lc8 = (tid & 3) * 8;

    for(int k0=0; k0<KB; k0+=32){
        const __nv_bfloat16 *ah, *al;
        if(k0 < PC){
            ah = &g_yh[(size_t)(row0+lr)*PC + k0 + lc8];
            al = &g_yl[(size_t)(row0+lr)*PC + k0 + lc8];
        } else {
            ah = &g_xh[(size_t)(row0+lr)*CC + (k0-PC) + lc8];
            al = &g_xl[(size_t)(row0+lr)*CC + (k0-PC) + lc8];
        }
        *(uint4*)&sm.mm.Ah[lr][lc8] = *(const uint4*)ah;
        *(uint4*)&sm.mm.Al[lr][lc8] = *(const uint4*)al;
        #pragma unroll
        for(int u=0;u<2;u++){
            int li = tid*2 + u;
            int br = li >> 2, bc8 = (li & 3) * 8;
            size_t wo = ((size_t)layer*CC + br)*KB + k0 + bc8;
            *(uint4*)&sm.mm.Bh[br][bc8] = *(const uint4*)&g_WBh[wo];
            *(uint4*)&sm.mm.Bl[br][bc8] = *(const uint4*)&g_WBl[wo];
        }
        __syncthreads();

        #pragma unroll
        for(int ks=0; ks<32; ks+=16){
            unsigned ah_[2][4], al_[2][4], bh_[4][2], bl_[4][2];
            #pragma unroll
            for(int i=0;i<2;i++){
                int r = wr0 + i*16 + gid;
                ah_[i][0] = *(const unsigned*)&sm.mm.Ah[r  ][ks   + 2*tig];
                ah_[i][1] = *(const unsigned*)&sm.mm.Ah[r+8][ks   + 2*tig];
                ah_[i][2] = *(const unsigned*)&sm.mm.Ah[r  ][ks+8 + 2*tig];
                ah_[i][3] = *(const unsigned*)&sm.mm.Ah[r+8][ks+8 + 2*tig];
                al_[i][0] = *(const unsigned*)&sm.mm.Al[r  ][ks   + 2*tig];
                al_[i][1] = *(const unsigned*)&sm.mm.Al[r+8][ks   + 2*tig];
                al_[i][2] = *(const unsigned*)&sm.mm.Al[r  ][ks+8 + 2*tig];
                al_[i][3] = *(const unsigned*)&sm.mm.Al[r+8][ks+8 + 2*tig];
            }
            #pragma unroll
            for(int j=0;j<4;j++){
                int c = wc0 + j*8 + gid;
                bh_[j][0] = *(const unsigned*)&sm.mm.Bh[c][ks   + 2*tig];
                bh_[j][1] = *(const unsigned*)&sm.mm.Bh[c][ks+8 + 2*tig];
                bl_[j][0] = *(const unsigned*)&sm.mm.Bl[c][ks   + 2*tig];
                bl_[j][1] = *(const unsigned*)&sm.mm.Bl[c][ks+8 + 2*tig];
            }
            #pragma unroll
            for(int i=0;i<2;i++)
                #pragma unroll
                for(int j=0;j<4;j++){
                    MMA16816(acc[i][j], ah_[i], bh_[j]);
                    MMA16816(acc[i][j], ah_[i], bl_[j]);
                    MMA16816(acc[i][j], al_[i], bh_[j]);
                }
        }
        __syncthreads();
    }

    // dump accumulators to smem
    #pragma unroll
    for(int i=0;i<2;i++){
        int r = wr0 + i*16 + gid;
        #pragma unroll
        for(int j=0;j<4;j++){
            int c = wc0 + j*8 + 2*tig;
            sm.C[r  ][c]   = acc[i][j][0];
            sm.C[r  ][c+1] = acc[i][j][1];
            sm.C[r+8][c]   = acc[i][j][2];
            sm.C[r+8][c+1] = acc[i][j][3];
        }
    }
    __syncthreads();

    // epilogue: +bias +bvm(if deg>0) +residual, LayerNorm, ReLU, bf16 split
    int row = tid >> 2, part = tid & 3;
    int n = row0 + row;
    float flag = (g_off[n+1] > g_off[n]) ? 1.f : 0.f;
    float s1 = 0.f;
    #pragma unroll
    for(int k=0;k<32;k++){
        int c = part*32 + k;
        float v = sm.C[row][c] + bs[c] + flag*g_bvm[layer*CC + c] + xold[(size_t)n*CC + c];
        sm.C[row][c] = v;
        s1 += v;
    }
    s1 += __shfl_xor_sync(0xffffffffu, s1, 1);
    s1 += __shfl_xor_sync(0xffffffffu, s1, 2);
    float mean = s1 * (1.f/CC);
    float s2 = 0.f;
    #pragma unroll
    for(int k=0;k<32;k++){
        float dv = sm.C[row][part*32 + k] - mean;
        s2 += dv*dv;
    }
    s2 += __shfl_xor_sync(0xffffffffu, s2, 1);
    s2 += __shfl_xor_sync(0xffffffffu, s2, 2);
    float inv = rsqrtf(s2*(1.f/CC) + 1e-5f);
    #pragma unroll
    for(int k=0;k<32;k++){
        int c = part*32 + k;
        float yv = (sm.C[row][c] - mean)*inv*lg[c] + lb[c];
        yv = fmaxf(yv, 0.f);
        xo[(size_t)n*CC + c] = yv;
        __nv_bfloat16 hh = __float2bfloat16(yv);
        g_xh[(size_t)n*CC + c] = hh;
        g_xl[(size_t)n*CC + c] = __float2bfloat16(yv - __bfloat162float(hh));
    }
}

// ---------------- output MLP on supernodes -----------------------------------
__global__ void mlp_kernel(int sel, const float* __restrict__ W, const float* __restrict__ b){
    const float* in  = sel ? g_m1 : g_x;
    float*       out = sel ? g_m2 : g_m1;
    __shared__ float row[CC];
    int g = blockIdx.x, c = threadIdx.x;
    row[c] = in[(size_t)g*CC + c];
    __syncthreads();
    float acc = b[c];
    const float* w = &W[(size_t)c*CC];
    #pragma unroll 8
    for(int k2=0;k2<CC;k2++) acc += row[k2]*w[k2];
    out[(size_t)g*CC + c] = fmaxf(acc, 0.f);
}

__global__ void final_kernel(const float* __restrict__ Wp, const float* __restrict__ bp,
                             float* __restrict__ out){
    int warp = (blockIdx.x*blockDim.x + threadIdx.x) >> 5;
    int lane = threadIdx.x & 31;
    if(warp >= GG) return;
    float a = 0.f;
    #pragma unroll
    for(int i=0;i<4;i++){
        int c = lane + 32*i;
        a += g_m2[(size_t)warp*CC + c] * Wp[c];
    }
    #pragma unroll
    for(int o=16;o>0;o>>=1) a += __shfl_xor_sync(0xffffffffu, a, o);
    if(lane==0) out[warp] = a + bp[0];
}

// ---------------- launch -----------------------------------------------------
extern "C" void kernel_launch(void* const* d_in, const int* in_sizes, int n_in,
                              void* d_out, int out_size)
{
    const int*   atoms = (const int*)d_in[0];
    const int*   ei    = (const int*)d_in[1];
    const int*   src   = ei;
    const int*   dstp  = ei + EE;
    const float* embd  = (const float*)d_in[2];
    const float* Wq    = (const float*)d_in[3];
    const float* bq    = (const float*)d_in[4];
    const float* Wk    = (const float*)d_in[5];
    const float* bk    = (const float*)d_in[6];  (void)bk; // softmax-invariant
    const float* Wv    = (const float*)d_in[7];
    const float* bv    = (const float*)d_in[8];
    const float* Ws    = (const float*)d_in[9];
    const float* bs    = (const float*)d_in[10];
    const float* lg    = (const float*)d_in[11];
    const float* lb    = (const float*)d_in[12];
    const float* Wlin  = (const float*)d_in[13];
    const float* blin  = (const float*)d_in[14];
    const float* Wp    = (const float*)d_in[15];
    const float* bp    = (const float*)d_in[16];
    float* out = (float*)d_out;

    prep_kernel<<<10282, 128>>>(Wq, Wk, Wv, Ws, bq, bv);      // 1
    hist_kernel<<<EE/256, 256>>>(dstp);                        // 2
    scan_kernel<<<1, 1024>>>();                                // 3
    scatter_kernel<<<EE/256, 256>>>(dstp);                     // 4
    embed_kernel<<<NN*CC/256, 256>>>(atoms, embd);             // 5

    for(int l=0; l<LL; l++){
        int parity = l & 1;
        gemm_p<<<dim3(PC/64, NN/64), 256>>>(l);                // 6 on l=0 (ncu target)
        attn_kernel<<<NN/8, 256>>>(parity, src);
        gemm_b<<<NN/64, 256>>>(l, parity, bs + (size_t)l*CC,
                               lg + (size_t)l*CC, lb + (size_t)l*CC);
    }

    mlp_kernel<<<GG, CC>>>(0, Wlin,         blin);
    mlp_kernel<<<GG, CC>>>(1, Wlin + CC*CC, blin + CC);
    final_kernel<<<GG*32/256, 256>>>(Wp, bp, out);
}

// round 4
// speedup vs baseline: 2.1752x; 1.0898x over previous
#include <cuda_runtime.h>
#include <cuda_bf16.h>
#include <math.h>

#define NN 32768
#define EE 131072
#define HH 6
#define CC 128
#define LL 6
#define GG 2048
#define PC 768      // p / y width (H*C)
#define KB 896      // gemm B K dim (768 y + 128 x)

// ---------------- scratch (device globals) -----------------------------------
__device__ float g_x[NN*CC];
__device__ float g_xn[NN*CC];
__device__ __nv_bfloat16 g_xh[NN*CC];
__device__ __nv_bfloat16 g_xl[NN*CC];
__device__ __nv_bfloat16 g_pb[NN*PC];       // p, bf16, 1/sqrt(C) folded
__device__ __nv_bfloat16 g_yh[NN*PC];
__device__ __nv_bfloat16 g_yl[NN*PC];
__device__ __nv_bfloat16 g_WAh[LL*PC*CC];   // Wqk = Wk^T Wq per head, bf16
__device__ float g_bqk[LL*PC];
__device__ __nv_bfloat16 g_WBh[LL*CC*KB];   // [Wv/H | Ws^T] combined, bf16 hi
__device__ __nv_bfloat16 g_WBl[LL*CC*KB];
__device__ float g_bvm[LL*CC];              // mean_h bv
__device__ int   g_deg[NN];
__device__ int   g_cnt[NN];
__device__ int   g_off[NN+1];
__device__ int   g_srcs[EE];                // CSR-ordered source node ids
__device__ float g_m1[GG*CC];
__device__ float g_m2[GG*CC];

// ---------------- prep: fold weights + zero counters (single launch) ---------
__global__ void prep_kernel(
    const float* __restrict__ Wq, const float* __restrict__ Wk,
    const float* __restrict__ Wv, const float* __restrict__ Ws,
    const float* __restrict__ bq, const float* __restrict__ bv)
{
    int bid = blockIdx.x, tid = threadIdx.x;
    if(bid < 4608){
        // Wqk_h[c,c2] = sum_cc Wk[h*128+cc, c] * Wq[h*128+cc, c2]
        int l = bid / (HH*CC);
        int rem = bid % (HH*CC);
        int h = rem >> 7, c = rem & 127;
        __shared__ float wk[128];
        wk[tid] = Wk[((size_t)l*PC + h*CC + tid)*CC + c];
        __syncthreads();
        float acc = 0.f;
        const float* wqp = &Wq[((size_t)l*PC + h*CC)*CC + tid];
        #pragma unroll 8
        for(int cc=0; cc<CC; cc++) acc += wk[cc] * wqp[(size_t)cc*CC];
        g_WAh[((size_t)l*PC + h*CC + c)*CC + tid] = __float2bfloat16(acc);
    } else if(bid < 4644){
        int b2 = bid - 4608;
        int l = b2 / HH, h = b2 % HH;
        float acc = 0.f;
        for(int cc=0; cc<CC; cc++)
            acc += bq[l*PC + h*CC + cc] * Wk[((size_t)l*PC + h*CC + cc)*CC + tid];
        g_bqk[l*PC + h*CC + tid] = acc;
    } else if(bid < 10020){
        int idx = (bid-4644)*128 + tid;          // over LL*CC*KB
        int l = idx / (CC*KB);
        int j = (idx / KB) % CC;
        int c = idx % KB;
        float v;
        if(c < PC){
            int h = c >> 7, cp = c & 127;
            v = Wv[((size_t)l*PC + h*CC + j)*CC + cp] * (1.f/HH);
        } else {
            v = Ws[((size_t)l*CC + j)*CC + (c - PC)];
        }
        size_t o = ((size_t)l*CC + j)*KB + c;
        __nv_bfloat16 hi = __float2bfloat16(v);
        g_WBh[o] = hi;
        g_WBl[o] = __float2bfloat16(v - __bfloat162float(hi));
    } else if(bid < 10276){
        int i = (bid-10020)*128 + tid;
        g_deg[i]=0; g_cnt[i]=0;
    } else {
        int i = (bid-10276)*128 + tid;           // LL*CC
        int l = i >> 7, j = i & 127;
        float a = 0.f;
        #pragma unroll
        for(int h=0;h<HH;h++) a += bv[l*PC + h*CC + j];
        g_bvm[i] = a * (1.f/HH);
    }
}

// ---------------- CSR build --------------------------------------------------
__global__ void hist_kernel(const int* __restrict__ dst){
    int e = blockIdx.x*blockDim.x + threadIdx.x;
    if(e < EE) atomicAdd(&g_deg[dst[e]], 1);
}
__global__ void scan_kernel(){
    __shared__ int sh[1024];
    __shared__ int sbase;
    int tid = threadIdx.x;
    if(tid==0){ sbase = 0; g_off[0] = 0; }
    __syncthreads();
    for(int chunk=0; chunk<NN/1024; chunk++){
        int idx = chunk*1024 + tid;
        sh[tid] = g_deg[idx];
        __syncthreads();
        for(int o=1;o<1024;o<<=1){
            int t = (tid>=o) ? sh[tid-o] : 0;
            __syncthreads();
            sh[tid] += t;
            __syncthreads();
        }
        g_off[idx+1] = sbase + sh[tid];
        __syncthreads();
        if(tid==1023) sbase += sh[1023];
        __syncthreads();
    }
}
__global__ void scatter_kernel(const int* __restrict__ src, const int* __restrict__ dst){
    int e = blockIdx.x*blockDim.x + threadIdx.x;
    if(e < EE){
        int d = dst[e];
        int pos = g_off[d] + atomicAdd(&g_cnt[d], 1);
        g_srcs[pos] = src[e];
    }
}

// ---------------- embedding (+ bf16 split) -----------------------------------
__global__ void embed_kernel(const int* __restrict__ atoms, const float* __restrict__ embd){
    int i = blockIdx.x*blockDim.x + threadIdx.x;
    int n = i >> 7, c = i & 127;
    float v = embd[atoms[n]*CC + c];
    g_x[i] = v;
    __nv_bfloat16 h = __float2bfloat16(v);
    g_xh[i] = h;
    g_xl[i] = __float2bfloat16(v - __bfloat162float(h));
}

// ---------------- MMA macro (bf16, fp32 accum) -------------------------------
#define MMA16816(d, a, b) asm volatile( \
    "mma.sync.aligned.m16n8k16.row.col.f32.bf16.bf16.f32 " \
    "{%0,%1,%2,%3}, {%4,%5,%6,%7}, {%8,%9}, {%0,%1,%2,%3};" \
    : "+f"(d[0]),"+f"(d[1]),"+f"(d[2]),"+f"(d[3]) \
    : "r"(a[0]),"r"(a[1]),"r"(a[2]),"r"(a[3]), "r"(b[0]),"r"(b[1]))

// ---------------- GEMM A: p = (x @ Wqk^T + bqk)/sqrt(C), bf16 out ------------
__global__ __launch_bounds__(256) void gemm_p(int layer)
{
    __shared__ __nv_bfloat16 sAh[64][72], sBh[64][72];
    int col0 = blockIdx.x * 64;
    int row0 = blockIdx.y * 64;

    int tid  = threadIdx.x;
    int warp = tid >> 5, lane = tid & 31;
    int wm = warp >> 2, wn = warp & 3;
    int gid = lane >> 2, tig = lane & 3;
    int wr0 = wm * 32, wc0 = wn * 16;

    float acc[2][2][4];
    #pragma unroll
    for(int i=0;i<2;i++)
        #pragma unroll
        for(int j=0;j<2;j++)
            #pragma unroll
            for(int t=0;t<4;t++) acc[i][j][t] = 0.f;

    int lr = tid >> 2;
    int lc = (tid & 3) * 16;
    const __nv_bfloat16* Ah = &g_xh[(size_t)(row0+lr)*CC + lc];
    const __nv_bfloat16* Bh = &g_WAh[((size_t)layer*PC + col0 + lr)*CC + lc];

    #pragma unroll
    for(int kit=0; kit<2; kit++){
        int k0 = kit * 64;
        *(uint4*)&sAh[lr][lc]   = *(const uint4*)(Ah + k0);
        *(uint4*)&sAh[lr][lc+8] = *(const uint4*)(Ah + k0 + 8);
        *(uint4*)&sBh[lr][lc]   = *(const uint4*)(Bh + k0);
        *(uint4*)&sBh[lr][lc+8] = *(const uint4*)(Bh + k0 + 8);
        __syncthreads();

        #pragma unroll
        for(int ks=0; ks<64; ks+=16){
            unsigned ah[2][4], bh[2][2];
            #pragma unroll
            for(int i=0;i<2;i++){
                int r = wr0 + i*16 + gid;
                ah[i][0] = *(const unsigned*)&sAh[r  ][ks   + 2*tig];
                ah[i][1] = *(const unsigned*)&sAh[r+8][ks   + 2*tig];
                ah[i][2] = *(const unsigned*)&sAh[r  ][ks+8 + 2*tig];
                ah[i][3] = *(const unsigned*)&sAh[r+8][ks+8 + 2*tig];
            }
            #pragma unroll
            for(int j=0;j<2;j++){
                int c = wc0 + j*8 + gid;
                bh[j][0] = *(const unsigned*)&sBh[c][ks   + 2*tig];
                bh[j][1] = *(const unsigned*)&sBh[c][ks+8 + 2*tig];
            }
            #pragma unroll
            for(int i=0;i<2;i++)
                #pragma unroll
                for(int j=0;j<2;j++)
                    MMA16816(acc[i][j], ah[i], bh[j]);
        }
        __syncthreads();
    }

    const float invsq = 0.08838834764831845f;  // 1/sqrt(128)
    #pragma unroll
    for(int i=0;i<2;i++){
        int r = row0 + wr0 + i*16 + gid;
        #pragma unroll
        for(int j=0;j<2;j++){
            int c = col0 + wc0 + j*8 + 2*tig;
            float b0 = g_bqk[layer*PC + c], b1 = g_bqk[layer*PC + c + 1];
            __nv_bfloat162 v0 = __nv_bfloat162(
                __float2bfloat16((acc[i][j][0] + b0)*invsq),
                __float2bfloat16((acc[i][j][1] + b1)*invsq));
            __nv_bfloat162 v1 = __nv_bfloat162(
                __float2bfloat16((acc[i][j][2] + b0)*invsq),
                __float2bfloat16((acc[i][j][3] + b1)*invsq));
            *(__nv_bfloat162*)&g_pb[(size_t)r*PC + c]     = v0;
            *(__nv_bfloat162*)&g_pb[(size_t)(r+8)*PC + c] = v1;
        }
    }
}

// ---------------- attention: single-pass online softmax, aggregate x ---------
__global__ __launch_bounds__(256) void attn_kernel(int parity)
{
    const float4* x4 = (const float4*)(parity ? g_xn : g_x);
    int warp = (blockIdx.x*blockDim.x + threadIdx.x) >> 5;
    int lane = threadIdx.x & 31;
    if(warp >= NN) return;
    int d = warp;

    // load p (bf16, pre-scaled) -> fp32 regs
    const __nv_bfloat162* pb = (const __nv_bfloat162*)&g_pb[(size_t)d*PC];
    float4 p[HH];
    #pragma unroll
    for(int h=0;h<HH;h++){
        float2 f0 = __bfloat1622float2(pb[h*64 + lane*2]);
        float2 f1 = __bfloat1622float2(pb[h*64 + lane*2 + 1]);
        p[h] = make_float4(f0.x, f0.y, f1.x, f1.y);
    }

    int e0 = g_off[d], e1 = g_off[d+1];
    float m[HH], den[HH];
    float4 y[HH];
    #pragma unroll
    for(int h=0;h<HH;h++){ m[h]=-1e30f; den[h]=0.f; y[h]=make_float4(0.f,0.f,0.f,0.f); }

    for(int t=e0; t<e1; t++){
        int s = g_srcs[t];
        float4 xv = x4[(size_t)s*32 + lane];
        float dot[HH];
        #pragma unroll
        for(int h=0;h<HH;h++)
            dot[h] = p[h].x*xv.x + p[h].y*xv.y + p[h].z*xv.z + p[h].w*xv.w;
        #pragma unroll
        for(int h=0;h<HH;h++){
            #pragma unroll
            for(int o=16;o>0;o>>=1) dot[h] += __shfl_xor_sync(0xffffffffu, dot[h], o);
        }
        #pragma unroll
        for(int h=0;h<HH;h++){
            float mn = fmaxf(m[h], dot[h]);
            float corr = __expf(m[h] - mn);
            float ex   = __expf(dot[h] - mn);
            den[h] = den[h]*corr + ex;
            y[h].x = y[h].x*corr + ex*xv.x;
            y[h].y = y[h].y*corr + ex*xv.y;
            y[h].z = y[h].z*corr + ex*xv.z;
            y[h].w = y[h].w*corr + ex*xv.w;
            m[h] = mn;
        }
    }

    // normalize, bf16-split store y
    size_t base = (size_t)d*PC;
    #pragma unroll
    for(int h=0;h<HH;h++){
        float r = (den[h] > 0.f) ? 1.f/den[h] : 0.f;
        float v0=y[h].x*r, v1=y[h].y*r, v2=y[h].z*r, v3=y[h].w*r;
        int c = h*CC + lane*4;
        __nv_bfloat16 h0=__float2bfloat16(v0), h1=__float2bfloat16(v1);
        __nv_bfloat16 h2=__float2bfloat16(v2), h3=__float2bfloat16(v3);
        *(__nv_bfloat162*)&g_yh[base+c]   = __nv_bfloat162(h0, h1);
        *(__nv_bfloat162*)&g_yh[base+c+2] = __nv_bfloat162(h2, h3);
        __nv_bfloat16 l0=__float2bfloat16(v0-__bfloat162float(h0));
        __nv_bfloat16 l1=__float2bfloat16(v1-__bfloat162float(h1));
        __nv_bfloat16 l2=__float2bfloat16(v2-__bfloat162float(h2));
        __nv_bfloat16 l3=__float2bfloat16(v3-__bfloat162float(h3));
        *(__nv_bfloat162*)&g_yl[base+c]   = __nv_bfloat162(l0, l1);
        *(__nv_bfloat162*)&g_yl[base+c+2] = __nv_bfloat162(l2, l3);
    }
}

// ---------------- GEMM B: out = [y|x] @ WB^T (+bias,+res) -> LN -> ReLU ------
__global__ __launch_bounds__(256) void gemm_b(
    int layer, int parity,
    const float* __restrict__ bs, const float* __restrict__ lg, const float* __restrict__ lb)
{
    const float* xold = parity ? g_xn : g_x;
    float*       xo   = parity ? g_x  : g_xn;
    __shared__ union {
        struct {
            __nv_bfloat16 Ah[64][40], Al[64][40];
            __nv_bfloat16 Bh[128][40], Bl[128][40];
        } mm;
        float C[64][132];
    } sm;
    int row0 = blockIdx.x * 64;
    int tid = threadIdx.x, warp = tid >> 5, lane = tid & 31;
    int wm = warp >> 2, wn = warp & 3;
    int gid = lane >> 2, tig = lane & 3;
    int wr0 = wm * 32, wc0 = wn * 32;

    float acc[2][4][4];
    #pragma unroll
    for(int i=0;i<2;i++)
        #pragma unroll
        for(int j=0;j<4;j++)
            #pragma unroll
            for(int t=0;t<4;t++) acc[i][j][t] = 0.f;

    int lr = tid >> 2, lc8 = (tid & 3) * 8;

    for(int k0=0; k0<KB; k0+=32){
        const __nv_bfloat16 *ah, *al;
        if(k0 < PC){
            ah = &g_yh[(size_t)(row0+lr)*PC + k0 + lc8];
            al = &g_yl[(size_t)(row0+lr)*PC + k0 + lc8];
        } else {
            ah = &g_xh[(size_t)(row0+lr)*CC + (k0-PC) + lc8];
            al = &g_xl[(size_t)(row0+lr)*CC + (k0-PC) + lc8];
        }
        *(uint4*)&sm.mm.Ah[lr][lc8] = *(const uint4*)ah;
        *(uint4*)&sm.mm.Al[lr][lc8] = *(const uint4*)al;
        #pragma unroll
        for(int u=0;u<2;u++){
            int li = tid*2 + u;
            int br = li >> 2, bc8 = (li & 3) * 8;
            size_t wo = ((size_t)layer*CC + br)*KB + k0 + bc8;
            *(uint4*)&sm.mm.Bh[br][bc8] = *(const uint4*)&g_WBh[wo];
            *(uint4*)&sm.mm.Bl[br][bc8] = *(const uint4*)&g_WBl[wo];
        }
        __syncthreads();

        #pragma unroll
        for(int ks=0; ks<32; ks+=16){
            unsigned ah_[2][4], al_[2][4], bh_[4][2], bl_[4][2];
            #pragma unroll
            for(int i=0;i<2;i++){
                int r = wr0 + i*16 + gid;
                ah_[i][0] = *(const unsigned*)&sm.mm.Ah[r  ][ks   + 2*tig];
                ah_[i][1] = *(const unsigned*)&sm.mm.Ah[r+8][ks   + 2*tig];
                ah_[i][2] = *(const unsigned*)&sm.mm.Ah[r  ][ks+8 + 2*tig];
                ah_[i][3] = *(const unsigned*)&sm.mm.Ah[r+8][ks+8 + 2*tig];
                al_[i][0] = *(const unsigned*)&sm.mm.Al[r  ][ks   + 2*tig];
                al_[i][1] = *(const unsigned*)&sm.mm.Al[r+8][ks   + 2*tig];
                al_[i][2] = *(const unsigned*)&sm.mm.Al[r  ][ks+8 + 2*tig];
                al_[i][3] = *(const unsigned*)&sm.mm.Al[r+8][ks+8 + 2*tig];
            }
            #pragma unroll
            for(int j=0;j<4;j++){
                int c = wc0 + j*8 + gid;
                bh_[j][0] = *(const unsigned*)&sm.mm.Bh[c][ks   + 2*tig];
                bh_[j][1] = *(const unsigned*)&sm.mm.Bh[c][ks+8 + 2*tig];
                bl_[j][0] = *(const unsigned*)&sm.mm.Bl[c][ks   + 2*tig];
                bl_[j][1] = *(const unsigned*)&sm.mm.Bl[c][ks+8 + 2*tig];
            }
            #pragma unroll
            for(int i=0;i<2;i++)
                #pragma unroll
                for(int j=0;j<4;j++){
                    MMA16816(acc[i][j], ah_[i], bh_[j]);
                    MMA16816(acc[i][j], ah_[i], bl_[j]);
                    MMA16816(acc[i][j], al_[i], bh_[j]);
                }
        }
        __syncthreads();
    }

    // dump accumulators to smem
    #pragma unroll
    for(int i=0;i<2;i++){
        int r = wr0 + i*16 + gid;
        #pragma unroll
        for(int j=0;j<4;j++){
            int c = wc0 + j*8 + 2*tig;
            sm.C[r  ][c]   = acc[i][j][0];
            sm.C[r  ][c+1] = acc[i][j][1];
            sm.C[r+8][c]   = acc[i][j][2];
            sm.C[r+8][c+1] = acc[i][j][3];
        }
    }
    __syncthreads();

    // epilogue: +bias +bvm(if deg>0) +residual, LayerNorm, ReLU, bf16 split
    int row = tid >> 2, part = tid & 3;
    int n = row0 + row;
    float flag = (g_off[n+1] > g_off[n]) ? 1.f : 0.f;
    float s1 = 0.f;
    #pragma unroll
    for(int k=0;k<32;k++){
        int c = part*32 + k;
        float v = sm.C[row][c] + bs[c] + flag*g_bvm[layer*CC + c] + xold[(size_t)n*CC + c];
        sm.C[row][c] = v;
        s1 += v;
    }
    s1 += __shfl_xor_sync(0xffffffffu, s1, 1);
    s1 += __shfl_xor_sync(0xffffffffu, s1, 2);
    float mean = s1 * (1.f/CC);
    float s2 = 0.f;
    #pragma unroll
    for(int k=0;k<32;k++){
        float dv = sm.C[row][part*32 + k] - mean;
        s2 += dv*dv;
    }
    s2 += __shfl_xor_sync(0xffffffffu, s2, 1);
    s2 += __shfl_xor_sync(0xffffffffu, s2, 2);
    float inv = rsqrtf(s2*(1.f/CC) + 1e-5f);
    #pragma unroll
    for(int k=0;k<32;k++){
        int c = part*32 + k;
        float yv = (sm.C[row][c] - mean)*inv*lg[c] + lb[c];
        yv = fmaxf(yv, 0.f);
        xo[(size_t)n*CC + c] = yv;
        __nv_bfloat16 hh = __float2bfloat16(yv);
        g_xh[(size_t)n*CC + c] = hh;
        g_xl[(size_t)n*CC + c] = __float2bfloat16(yv - __bfloat162float(hh));
    }
}

// ---------------- output MLP on supernodes -----------------------------------
__global__ void mlp_kernel(int sel, const float* __restrict__ W, const float* __restrict__ b){
    const float* in  = sel ? g_m1 : g_x;
    float*       out = sel ? g_m2 : g_m1;
    __shared__ float row[CC];
    int g = blockIdx.x, c = threadIdx.x;
    row[c] = in[(size_t)g*CC + c];
    __syncthreads();
    float acc = b[c];
    const float* w = &W[(size_t)c*CC];
    #pragma unroll 8
    for(int k2=0;k2<CC;k2++) acc += row[k2]*w[k2];
    out[(size_t)g*CC + c] = fmaxf(acc, 0.f);
}

__global__ void final_kernel(const float* __restrict__ Wp, const float* __restrict__ bp,
                             float* __restrict__ out){
    int warp = (blockIdx.x*blockDim.x + threadIdx.x) >> 5;
    int lane = threadIdx.x & 31;
    if(warp >= GG) return;
    float a = 0.f;
    #pragma unroll
    for(int i=0;i<4;i++){
        int c = lane + 32*i;
        a += g_m2[(size_t)warp*CC + c] * Wp[c];
    }
    #pragma unroll
    for(int o=16;o>0;o>>=1) a += __shfl_xor_sync(0xffffffffu, a, o);
    if(lane==0) out[warp] = a + bp[0];
}

// ---------------- launch -----------------------------------------------------
extern "C" void kernel_launch(void* const* d_in, const int* in_sizes, int n_in,
                              void* d_out, int out_size)
{
    const int*   atoms = (const int*)d_in[0];
    const int*   ei    = (const int*)d_in[1];
    const int*   src   = ei;
    const int*   dstp  = ei + EE;
    const float* embd  = (const float*)d_in[2];
    const float* Wq    = (const float*)d_in[3];
    const float* bq    = (const float*)d_in[4];
    const float* Wk    = (const float*)d_in[5];
    const float* bk    = (const float*)d_in[6];  (void)bk; // softmax-invariant
    const float* Wv    = (const float*)d_in[7];
    const float* bv    = (const float*)d_in[8];
    const float* Ws    = (const float*)d_in[9];
    const float* bs    = (const float*)d_in[10];
    const float* lg    = (const float*)d_in[11];
    const float* lb    = (const float*)d_in[12];
    const float* Wlin  = (const float*)d_in[13];
    const float* blin  = (const float*)d_in[14];
    const float* Wp    = (const float*)d_in[15];
    const float* bp    = (const float*)d_in[16];
    float* out = (float*)d_out;

    // order chosen so my 4th launch (= 6th overall incl. harness) is gemm_p(l=0)
    prep_kernel<<<10282, 128>>>(Wq, Wk, Wv, Ws, bq, bv);       // 1
    embed_kernel<<<NN*CC/256, 256>>>(atoms, embd);             // 2
    hist_kernel<<<EE/256, 256>>>(dstp);                        // 3
    gemm_p<<<dim3(PC/64, NN/64), 256>>>(0);                    // 4  <- ncu target
    scan_kernel<<<1, 1024>>>();                                // 5
    scatter_kernel<<<EE/256, 256>>>(src, dstp);                // 6
    attn_kernel<<<NN/8, 256>>>(0);                             // 7
    gemm_b<<<NN/64, 256>>>(0, 0, bs, lg, lb);                  // 8

    for(int l=1; l<LL; l++){
        int parity = l & 1;
        gemm_p<<<dim3(PC/64, NN/64), 256>>>(l);
        attn_kernel<<<NN/8, 256>>>(parity);
        gemm_b<<<NN/64, 256>>>(l, parity, bs + (size_t)l*CC,
                               lg + (size_t)l*CC, lb + (size_t)l*CC);
    }

    mlp_kernel<<<GG, CC>>>(0, Wlin,         blin);
    mlp_kernel<<<GG, CC>>>(1, Wlin + CC*CC, blin + CC);
    final_kernel<<<GG*32/256, 256>>>(Wp, bp, out);
}

// round 5
// speedup vs baseline: 2.2208x; 1.0210x over previous
#include <cuda_runtime.h>
#include <cuda_bf16.h>
#include <math.h>

#define NN 32768
#define EE 131072
#define HH 6
#define CC 128
#define LL 6
#define GG 2048
#define PC 768      // p / y width (H*C)
#define KB 896      // gemm B K dim (768 y + 128 x)

// ---------------- scratch (device globals) -----------------------------------
__device__ float g_x[NN*CC];
__device__ float g_xn[NN*CC];
__device__ __nv_bfloat16 g_xh[NN*CC];
__device__ __nv_bfloat16 g_xl[NN*CC];
__device__ __nv_bfloat16 g_pb[NN*PC];       // p, bf16, 1/sqrt(C) folded
__device__ __nv_bfloat16 g_yh[NN*PC];
__device__ __nv_bfloat16 g_yl[NN*PC];
__device__ __nv_bfloat16 g_WAh[LL*PC*CC];   // Wqk = Wk^T Wq per head, bf16
__device__ float g_bqk[LL*PC];
__device__ __nv_bfloat16 g_WBh[LL*CC*KB];   // [Wv/H | Ws^T] combined, bf16 hi
__device__ __nv_bfloat16 g_WBl[LL*CC*KB];
__device__ float g_bvm[LL*CC];              // mean_h bv
__device__ int   g_deg[NN];
__device__ int   g_cnt[NN];
__device__ int   g_off[NN+1];
__device__ int   g_srcs[EE];                // CSR-ordered source node ids
__device__ float g_m1[GG*CC];
__device__ float g_m2[GG*CC];

// ---------------- prep: fold weights + zero counters (single launch) ---------
__global__ void prep_kernel(
    const float* __restrict__ Wq, const float* __restrict__ Wk,
    const float* __restrict__ Wv, const float* __restrict__ Ws,
    const float* __restrict__ bq, const float* __restrict__ bv)
{
    int bid = blockIdx.x, tid = threadIdx.x;
    if(bid < 4608){
        // Wqk_h[c,c2] = sum_cc Wk[h*128+cc, c] * Wq[h*128+cc, c2]
        int l = bid / (HH*CC);
        int rem = bid % (HH*CC);
        int h = rem >> 7, c = rem & 127;
        __shared__ float wk[128];
        wk[tid] = Wk[((size_t)l*PC + h*CC + tid)*CC + c];
        __syncthreads();
        float acc = 0.f;
        const float* wqp = &Wq[((size_t)l*PC + h*CC)*CC + tid];
        #pragma unroll 8
        for(int cc=0; cc<CC; cc++) acc += wk[cc] * wqp[(size_t)cc*CC];
        g_WAh[((size_t)l*PC + h*CC + c)*CC + tid] = __float2bfloat16(acc);
    } else if(bid < 4644){
        int b2 = bid - 4608;
        int l = b2 / HH, h = b2 % HH;
        float acc = 0.f;
        for(int cc=0; cc<CC; cc++)
            acc += bq[l*PC + h*CC + cc] * Wk[((size_t)l*PC + h*CC + cc)*CC + tid];
        g_bqk[l*PC + h*CC + tid] = acc;
    } else if(bid < 10020){
        int idx = (bid-4644)*128 + tid;          // over LL*CC*KB
        int l = idx / (CC*KB);
        int j = (idx / KB) % CC;
        int c = idx % KB;
        float v;
        if(c < PC){
            int h = c >> 7, cp = c & 127;
            v = Wv[((size_t)l*PC + h*CC + j)*CC + cp] * (1.f/HH);
        } else {
            v = Ws[((size_t)l*CC + j)*CC + (c - PC)];
        }
        size_t o = ((size_t)l*CC + j)*KB + c;
        __nv_bfloat16 hi = __float2bfloat16(v);
        g_WBh[o] = hi;
        g_WBl[o] = __float2bfloat16(v - __bfloat162float(hi));
    } else if(bid < 10276){
        int i = (bid-10020)*128 + tid;
        g_deg[i]=0; g_cnt[i]=0;
    } else {
        int i = (bid-10276)*128 + tid;           // LL*CC
        int l = i >> 7, j = i & 127;
        float a = 0.f;
        #pragma unroll
        for(int h=0;h<HH;h++) a += bv[l*PC + h*CC + j];
        g_bvm[i] = a * (1.f/HH);
    }
}

// ---------------- CSR build --------------------------------------------------
__global__ void hist_kernel(const int* __restrict__ dst){
    int e = blockIdx.x*blockDim.x + threadIdx.x;
    if(e < EE) atomicAdd(&g_deg[dst[e]], 1);
}
__global__ void scan_kernel(){
    __shared__ int sh[1024];
    __shared__ int sbase;
    int tid = threadIdx.x;
    if(tid==0){ sbase = 0; g_off[0] = 0; }
    __syncthreads();
    for(int chunk=0; chunk<NN/1024; chunk++){
        int idx = chunk*1024 + tid;
        sh[tid] = g_deg[idx];
        __syncthreads();
        for(int o=1;o<1024;o<<=1){
            int t = (tid>=o) ? sh[tid-o] : 0;
            __syncthreads();
            sh[tid] += t;
            __syncthreads();
        }
        g_off[idx+1] = sbase + sh[tid];
        __syncthreads();
        if(tid==1023) sbase += sh[1023];
        __syncthreads();
    }
}
__global__ void scatter_kernel(const int* __restrict__ src, const int* __restrict__ dst){
    int e = blockIdx.x*blockDim.x + threadIdx.x;
    if(e < EE){
        int d = dst[e];
        int pos = g_off[d] + atomicAdd(&g_cnt[d], 1);
        g_srcs[pos] = src[e];
    }
}

// ---------------- embedding (+ bf16 split) -----------------------------------
__global__ void embed_kernel(const int* __restrict__ atoms, const float* __restrict__ embd){
    int i = blockIdx.x*blockDim.x + threadIdx.x;
    int n = i >> 7, c = i & 127;
    float v = embd[atoms[n]*CC + c];
    g_x[i] = v;
    __nv_bfloat16 h = __float2bfloat16(v);
    g_xh[i] = h;
    g_xl[i] = __float2bfloat16(v - __bfloat162float(h));
}

// ---------------- MMA / LDSM macros ------------------------------------------
#define MMA16816(d, a, b) asm volatile( \
    "mma.sync.aligned.m16n8k16.row.col.f32.bf16.bf16.f32 " \
    "{%0,%1,%2,%3}, {%4,%5,%6,%7}, {%8,%9}, {%0,%1,%2,%3};" \
    : "+f"(d[0]),"+f"(d[1]),"+f"(d[2]),"+f"(d[3]) \
    : "r"(a[0]),"r"(a[1]),"r"(a[2]),"r"(a[3]), "r"(b[0]),"r"(b[1]))

#define LDSM_X4(R0,R1,R2,R3,A) asm volatile( \
    "ldmatrix.sync.aligned.m8n8.x4.shared.b16 {%0,%1,%2,%3}, [%4];" \
    : "=r"(R0),"=r"(R1),"=r"(R2),"=r"(R3) : "r"(A))

__device__ __forceinline__ unsigned smem_u32p(const void* p){
    return (unsigned)__cvta_generic_to_shared(p);
}

// ---------------- GEMM A: p = (x @ Wqk^T + bqk)/sqrt(C), bf16 out ------------
__global__ __launch_bounds__(256) void gemm_p(int layer)
{
    __shared__ __nv_bfloat16 sAh[64][72], sBh[64][72];
    int col0 = blockIdx.x * 64;
    int row0 = blockIdx.y * 64;

    int tid  = threadIdx.x;
    int warp = tid >> 5, lane = tid & 31;
    int wm = warp >> 2, wn = warp & 3;
    int gid = lane >> 2, tig = lane & 3;
    int wr0 = wm * 32, wc0 = wn * 16;

    float acc[2][2][4];
    #pragma unroll
    for(int i=0;i<2;i++)
        #pragma unroll
        for(int j=0;j<2;j++)
            #pragma unroll
            for(int t=0;t<4;t++) acc[i][j][t] = 0.f;

    int lr = tid >> 2;
    int lc = (tid & 3) * 16;
    const __nv_bfloat16* Ah = &g_xh[(size_t)(row0+lr)*CC + lc];
    const __nv_bfloat16* Bh = &g_WAh[((size_t)layer*PC + col0 + lr)*CC + lc];

    // ldmatrix per-lane base addresses (fixed across k-steps)
    unsigned aAddr[2];
    #pragma unroll
    for(int i=0;i<2;i++)
        aAddr[i] = smem_u32p(&sAh[wr0 + i*16 + (lane & 15)][(lane >> 4) * 8]);
    unsigned bAddr = smem_u32p(&sBh[wc0 + (lane & 7) + (lane >> 4)*8][((lane >> 3) & 1) * 8]);

    #pragma unroll
    for(int kit=0; kit<2; kit++){
        int k0 = kit * 64;
        *(uint4*)&sAh[lr][lc]   = *(const uint4*)(Ah + k0);
        *(uint4*)&sAh[lr][lc+8] = *(const uint4*)(Ah + k0 + 8);
        *(uint4*)&sBh[lr][lc]   = *(const uint4*)(Bh + k0);
        *(uint4*)&sBh[lr][lc+8] = *(const uint4*)(Bh + k0 + 8);
        __syncthreads();

        #pragma unroll
        for(int ks=0; ks<64; ks+=16){
            unsigned ah[2][4], bb[4];
            LDSM_X4(ah[0][0], ah[0][1], ah[0][2], ah[0][3], aAddr[0] + ks*2);
            LDSM_X4(ah[1][0], ah[1][1], ah[1][2], ah[1][3], aAddr[1] + ks*2);
            LDSM_X4(bb[0], bb[1], bb[2], bb[3], bAddr + ks*2);
            unsigned b0[2] = {bb[0], bb[1]};
            unsigned b1[2] = {bb[2], bb[3]};
            #pragma unroll
            for(int i=0;i<2;i++){
                MMA16816(acc[i][0], ah[i], b0);
                MMA16816(acc[i][1], ah[i], b1);
            }
        }
        __syncthreads();
    }

    const float invsq = 0.08838834764831845f;  // 1/sqrt(128)
    #pragma unroll
    for(int i=0;i<2;i++){
        int r = row0 + wr0 + i*16 + gid;
        #pragma unroll
        for(int j=0;j<2;j++){
            int c = col0 + wc0 + j*8 + 2*tig;
            float b0 = g_bqk[layer*PC + c], b1 = g_bqk[layer*PC + c + 1];
            __nv_bfloat162 v0 = __nv_bfloat162(
                __float2bfloat16((acc[i][j][0] + b0)*invsq),
                __float2bfloat16((acc[i][j][1] + b1)*invsq));
            __nv_bfloat162 v1 = __nv_bfloat162(
                __float2bfloat16((acc[i][j][2] + b0)*invsq),
                __float2bfloat16((acc[i][j][3] + b1)*invsq));
            *(__nv_bfloat162*)&g_pb[(size_t)r*PC + c]     = v0;
            *(__nv_bfloat162*)&g_pb[(size_t)(r+8)*PC + c] = v1;
        }
    }
}

// ---------------- attention: single-pass online softmax, aggregate x ---------
__global__ __launch_bounds__(256) void attn_kernel(int parity)
{
    const float4* x4 = (const float4*)(parity ? g_xn : g_x);
    int warp = (blockIdx.x*blockDim.x + threadIdx.x) >> 5;
    int lane = threadIdx.x & 31;
    if(warp >= NN) return;
    int d = warp;

    // load p (bf16, pre-scaled) -> fp32 regs
    const __nv_bfloat162* pb = (const __nv_bfloat162*)&g_pb[(size_t)d*PC];
    float4 p[HH];
    #pragma unroll
    for(int h=0;h<HH;h++){
        float2 f0 = __bfloat1622float2(pb[h*64 + lane*2]);
        float2 f1 = __bfloat1622float2(pb[h*64 + lane*2 + 1]);
        p[h] = make_float4(f0.x, f0.y, f1.x, f1.y);
    }

    int e0 = g_off[d], e1 = g_off[d+1];
    float m[HH], den[HH];
    float4 y[HH];
    #pragma unroll
    for(int h=0;h<HH;h++){ m[h]=-1e30f; den[h]=0.f; y[h]=make_float4(0.f,0.f,0.f,0.f); }

    for(int t=e0; t<e1; t++){
        int s = g_srcs[t];
        float4 xv = x4[(size_t)s*32 + lane];
        float dot[HH];
        #pragma unroll
        for(int h=0;h<HH;h++)
            dot[h] = p[h].x*xv.x + p[h].y*xv.y + p[h].z*xv.z + p[h].w*xv.w;
        #pragma unroll
        for(int h=0;h<HH;h++){
            #pragma unroll
            for(int o=16;o>0;o>>=1) dot[h] += __shfl_xor_sync(0xffffffffu, dot[h], o);
        }
        #pragma unroll
        for(int h=0;h<HH;h++){
            float mn = fmaxf(m[h], dot[h]);
            float corr = __expf(m[h] - mn);
            float ex   = __expf(dot[h] - mn);
            den[h] = den[h]*corr + ex;
            y[h].x = y[h].x*corr + ex*xv.x;
            y[h].y = y[h].y*corr + ex*xv.y;
            y[h].z = y[h].z*corr + ex*xv.z;
            y[h].w = y[h].w*corr + ex*xv.w;
            m[h] = mn;
        }
    }

    // normalize, bf16-split store y
    size_t base = (size_t)d*PC;
    #pragma unroll
    for(int h=0;h<HH;h++){
        float r = (den[h] > 0.f) ? 1.f/den[h] : 0.f;
        float v0=y[h].x*r, v1=y[h].y*r, v2=y[h].z*r, v3=y[h].w*r;
        int c = h*CC + lane*4;
        __nv_bfloat16 h0=__float2bfloat16(v0), h1=__float2bfloat16(v1);
        __nv_bfloat16 h2=__float2bfloat16(v2), h3=__float2bfloat16(v3);
        *(__nv_bfloat162*)&g_yh[base+c]   = __nv_bfloat162(h0, h1);
        *(__nv_bfloat162*)&g_yh[base+c+2] = __nv_bfloat162(h2, h3);
        __nv_bfloat16 l0=__float2bfloat16(v0-__bfloat162float(h0));
        __nv_bfloat16 l1=__float2bfloat16(v1-__bfloat162float(h1));
        __nv_bfloat16 l2=__float2bfloat16(v2-__bfloat162float(h2));
        __nv_bfloat16 l3=__float2bfloat16(v3-__bfloat162float(h3));
        *(__nv_bfloat162*)&g_yl[base+c]   = __nv_bfloat162(l0, l1);
        *(__nv_bfloat162*)&g_yl[base+c+2] = __nv_bfloat162(l2, l3);
    }
}

// ---------------- GEMM B: out = [y|x] @ WB^T (+bias,+res) -> LN -> ReLU ------
__global__ __launch_bounds__(256) void gemm_b(
    int layer, int parity,
    const float* __restrict__ bs, const float* __restrict__ lg, const float* __restrict__ lb)
{
    const float* xold = parity ? g_xn : g_x;
    float*       xo   = parity ? g_x  : g_xn;
    __shared__ union {
        struct {
            __nv_bfloat16 Ah[64][40], Al[64][40];
            __nv_bfloat16 Bh[128][40], Bl[128][40];
        } mm;
        float C[64][132];
    } sm;
    int row0 = blockIdx.x * 64;
    int tid = threadIdx.x, warp = tid >> 5, lane = tid & 31;
    int wm = warp >> 2, wn = warp & 3;
    int gid = lane >> 2, tig = lane & 3;
    int wr0 = wm * 32, wc0 = wn * 32;

    float acc[2][4][4];
    #pragma unroll
    for(int i=0;i<2;i++)
        #pragma unroll
        for(int j=0;j<4;j++)
            #pragma unroll
            for(int t=0;t<4;t++) acc[i][j][t] = 0.f;

    int lr = tid >> 2, lc8 = (tid & 3) * 8;

    // ldmatrix per-lane base addresses (arrays stride 40 bf16; conflict-free)
    unsigned aAddrH[2], aAddrL[2], bAddrH[2], bAddrL[2];
    {
        int arow = (lane & 15), ak = (lane >> 4) * 8;
        #pragma unroll
        for(int i=0;i<2;i++){
            aAddrH[i] = smem_u32p(&sm.mm.Ah[wr0 + i*16 + arow][ak]);
            aAddrL[i] = smem_u32p(&sm.mm.Al[wr0 + i*16 + arow][ak]);
        }
        int bcol = (lane & 7) + (lane >> 4)*8;
        int bk = ((lane >> 3) & 1) * 8;
        #pragma unroll
        for(int g=0; g<2; g++){
            bAddrH[g] = smem_u32p(&sm.mm.Bh[wc0 + g*16 + bcol][bk]);
            bAddrL[g] = smem_u32p(&sm.mm.Bl[wc0 + g*16 + bcol][bk]);
        }
    }

    for(int k0=0; k0<KB; k0+=32){
        const __nv_bfloat16 *ah, *al;
        if(k0 < PC){
            ah = &g_yh[(size_t)(row0+lr)*PC + k0 + lc8];
            al = &g_yl[(size_t)(row0+lr)*PC + k0 + lc8];
        } else {
            ah = &g_xh[(size_t)(row0+lr)*CC + (k0-PC) + lc8];
            al = &g_xl[(size_t)(row0+lr)*CC + (k0-PC) + lc8];
        }
        *(uint4*)&sm.mm.Ah[lr][lc8] = *(const uint4*)ah;
        *(uint4*)&sm.mm.Al[lr][lc8] = *(const uint4*)al;
        #pragma unroll
        for(int u=0;u<2;u++){
            int li = tid*2 + u;
            int br = li >> 2, bc8 = (li & 3) * 8;
            size_t wo = ((size_t)layer*CC + br)*KB + k0 + bc8;
            *(uint4*)&sm.mm.Bh[br][bc8] = *(const uint4*)&g_WBh[wo];
            *(uint4*)&sm.mm.Bl[br][bc8] = *(const uint4*)&g_WBl[wo];
        }
        __syncthreads();

        #pragma unroll
        for(int ks=0; ks<32; ks+=16){
            unsigned ah_[2][4], al_[2][4], bh_[4][2], bl_[4][2];
            #pragma unroll
            for(int i=0;i<2;i++){
                LDSM_X4(ah_[i][0], ah_[i][1], ah_[i][2], ah_[i][3], aAddrH[i] + ks*2);
                LDSM_X4(al_[i][0], al_[i][1], al_[i][2], al_[i][3], aAddrL[i] + ks*2);
            }
            #pragma unroll
            for(int g=0; g<2; g++){
                LDSM_X4(bh_[g*2][0], bh_[g*2][1], bh_[g*2+1][0], bh_[g*2+1][1], bAddrH[g] + ks*2);
                LDSM_X4(bl_[g*2][0], bl_[g*2][1], bl_[g*2+1][0], bl_[g*2+1][1], bAddrL[g] + ks*2);
            }
            #pragma unroll
            for(int i=0;i<2;i++)
                #pragma unroll
                for(int j=0;j<4;j++){
                    MMA16816(acc[i][j], ah_[i], bh_[j]);
                    MMA16816(acc[i][j], ah_[i], bl_[j]);
                    MMA16816(acc[i][j], al_[i], bh_[j]);
                }
        }
        __syncthreads();
    }

    // dump accumulators to smem
    #pragma unroll
    for(int i=0;i<2;i++){
        int r = wr0 + i*16 + gid;
        #pragma unroll
        for(int j=0;j<4;j++){
            int c = wc0 + j*8 + 2*tig;
            sm.C[r  ][c]   = acc[i][j][0];
            sm.C[r  ][c+1] = acc[i][j][1];
            sm.C[r+8][c]   = acc[i][j][2];
            sm.C[r+8][c+1] = acc[i][j][3];
        }
    }
    __syncthreads();

    // epilogue: +bias +bvm(if deg>0) +residual, LayerNorm, ReLU, bf16 split
    int row = tid >> 2, part = tid & 3;
    int n = row0 + row;
    float flag = (g_off[n+1] > g_off[n]) ? 1.f : 0.f;
    float s1 = 0.f;
    #pragma unroll
    for(int k=0;k<32;k++){
        int c = part*32 + k;
        float v = sm.C[row][c] + bs[c] + flag*g_bvm[layer*CC + c] + xold[(size_t)n*CC + c];
        sm.C[row][c] = v;
        s1 += v;
    }
    s1 += __shfl_xor_sync(0xffffffffu, s1, 1);
    s1 += __shfl_xor_sync(0xffffffffu, s1, 2);
    float mean = s1 * (1.f/CC);
    float s2 = 0.f;
    #pragma unroll
    for(int k=0;k<32;k++){
        float dv = sm.C[row][part*32 + k] - mean;
        s2 += dv*dv;
    }
    s2 += __shfl_xor_sync(0xffffffffu, s2, 1);
    s2 += __shfl_xor_sync(0xffffffffu, s2, 2);
    float inv = rsqrtf(s2*(1.f/CC) + 1e-5f);
    #pragma unroll
    for(int k=0;k<32;k++){
        int c = part*32 + k;
        float yv = (sm.C[row][c] - mean)*inv*lg[c] + lb[c];
        yv = fmaxf(yv, 0.f);
        xo[(size_t)n*CC + c] = yv;
        __nv_bfloat16 hh = __float2bfloat16(yv);
        g_xh[(size_t)n*CC + c] = hh;
        g_xl[(size_t)n*CC + c] = __float2bfloat16(yv - __bfloat162float(hh));
    }
}

// ---------------- output MLP on supernodes -----------------------------------
__global__ void mlp_kernel(int sel, const float* __restrict__ W, const float* __restrict__ b){
    const float* in  = sel ? g_m1 : g_x;
    float*       out = sel ? g_m2 : g_m1;
    __shared__ float row[CC];
    int g = blockIdx.x, c = threadIdx.x;
    row[c] = in[(size_t)g*CC + c];
    __syncthreads();
    float acc = b[c];
    const float* w = &W[(size_t)c*CC];
    #pragma unroll 8
    for(int k2=0;k2<CC;k2++) acc += row[k2]*w[k2];
    out[(size_t)g*CC + c] = fmaxf(acc, 0.f);
}

__global__ void final_kernel(const float* __restrict__ Wp, const float* __restrict__ bp,
                             float* __restrict__ out){
    int warp = (blockIdx.x*blockDim.x + threadIdx.x) >> 5;
    int lane = threadIdx.x & 31;
    if(warp >= GG) return;
    float a = 0.f;
    #pragma unroll
    for(int i=0;i<4;i++){
        int c = lane + 32*i;
        a += g_m2[(size_t)warp*CC + c] * Wp[c];
    }
    #pragma unroll
    for(int o=16;o>0;o>>=1) a += __shfl_xor_sync(0xffffffffu, a, o);
    if(lane==0) out[warp] = a + bp[0];
}

// ---------------- launch -----------------------------------------------------
extern "C" void kernel_launch(void* const* d_in, const int* in_sizes, int n_in,
                              void* d_out, int out_size)
{
    const int*   atoms = (const int*)d_in[0];
    const int*   ei    = (const int*)d_in[1];
    const int*   src   = ei;
    const int*   dstp  = ei + EE;
    const float* embd  = (const float*)d_in[2];
    const float* Wq    = (const float*)d_in[3];
    const float* bq    = (const float*)d_in[4];
    const float* Wk    = (const float*)d_in[5];
    const float* bk    = (const float*)d_in[6];  (void)bk; // softmax-invariant
    const float* Wv    = (const float*)d_in[7];
    const float* bv    = (const float*)d_in[8];
    const float* Ws    = (const float*)d_in[9];
    const float* bs    = (const float*)d_in[10];
    const float* lg    = (const float*)d_in[11];
    const float* lb    = (const float*)d_in[12];
    const float* Wlin  = (const float*)d_in[13];
    const float* blin  = (const float*)d_in[14];
    const float* Wp    = (const float*)d_in[15];
    const float* bp    = (const float*)d_in[16];
    float* out = (float*)d_out;

    // order chosen so my 4th launch is gemm_p(l=0) (ncu -s 5 target)
    prep_kernel<<<10282, 128>>>(Wq, Wk, Wv, Ws, bq, bv);       // 1
    embed_kernel<<<NN*CC/256, 256>>>(atoms, embd);             // 2
    hist_kernel<<<EE/256, 256>>>(dstp);                        // 3
    gemm_p<<<dim3(PC/64, NN/64), 256>>>(0);                    // 4  <- ncu target
    scan_kernel<<<1, 1024>>>();                                // 5
    scatter_kernel<<<EE/256, 256>>>(src, dstp);                // 6
    attn_kernel<<<NN/8, 256>>>(0);                             // 7
    gemm_b<<<NN/64, 256>>>(0, 0, bs, lg, lb);                  // 8

    for(int l=1; l<LL; l++){
        int parity = l & 1;
        gemm_p<<<dim3(PC/64, NN/64), 256>>>(l);
        attn_kernel<<<NN/8, 256>>>(parity);
        gemm_b<<<NN/64, 256>>>(l, parity, bs + (size_t)l*CC,
                               lg + (size_t)l*CC, lb + (size_t)l*CC);
    }

    mlp_kernel<<<GG, CC>>>(0, Wlin,         blin);
    mlp_kernel<<<GG, CC>>>(1, Wlin + CC*CC, blin + CC);
    final_kernel<<<GG*32/256, 256>>>(Wp, bp, out);
}

// round 7
// speedup vs baseline: 2.7826x; 1.2530x over previous
#include <cuda_runtime.h>
#include <cuda_bf16.h>
#include <math.h>

#define NN 32768
#define EE 131072
#define HH 6
#define CC 128
#define LL 6
#define GG 2048
#define PC 768      // p / y width (H*C)
#define KB 896      // gemm B K dim (768 y + 128 x)

// ---------------- scratch (device globals) -----------------------------------
__device__ float g_x[NN*CC];
__device__ float g_xn[NN*CC];
__device__ __nv_bfloat16 g_xh[NN*CC];
__device__ __nv_bfloat16 g_xl[NN*CC];
__device__ __nv_bfloat16 g_pb[NN*PC];       // p, bf16, 1/sqrt(C) folded
__device__ __nv_bfloat16 g_yh[NN*PC];
__device__ __nv_bfloat16 g_yl[NN*PC];
__device__ __nv_bfloat16 g_WAh[LL*PC*CC];   // Wqk = Wk^T Wq per head, bf16
__device__ float g_bqk[LL*PC];
__device__ __nv_bfloat16 g_WBh[LL*CC*KB];   // [Wv/H | Ws^T] combined, bf16 hi
__device__ __nv_bfloat16 g_WBl[LL*CC*KB];
__device__ float g_bvm[LL*CC];              // mean_h bv
__device__ int   g_deg[NN];
__device__ int   g_cnt[NN];
__device__ int   g_off[NN+1];
__device__ int   g_srcs[EE];                // CSR-ordered source node ids
__device__ float g_m1[GG*CC];
__device__ float g_m2[GG*CC];

// ---------------- prep: fold weights + zero counters (single launch) ---------
__global__ void prep_kernel(
    const float* __restrict__ Wq, const float* __restrict__ Wk,
    const float* __restrict__ Wv, const float* __restrict__ Ws,
    const float* __restrict__ bq, const float* __restrict__ bv)
{
    int bid = blockIdx.x, tid = threadIdx.x;
    if(bid < 4608){
        // Wqk_h[c,c2] = sum_cc Wk[h*128+cc, c] * Wq[h*128+cc, c2]
        int l = bid / (HH*CC);
        int rem = bid % (HH*CC);
        int h = rem >> 7, c = rem & 127;
        __shared__ float wk[128];
        wk[tid] = Wk[((size_t)l*PC + h*CC + tid)*CC + c];
        __syncthreads();
        float acc = 0.f;
        const float* wqp = &Wq[((size_t)l*PC + h*CC)*CC + tid];
        #pragma unroll 8
        for(int cc=0; cc<CC; cc++) acc += wk[cc] * wqp[(size_t)cc*CC];
        g_WAh[((size_t)l*PC + h*CC + c)*CC + tid] = __float2bfloat16(acc);
    } else if(bid < 4644){
        int b2 = bid - 4608;
        int l = b2 / HH, h = b2 % HH;
        float acc = 0.f;
        for(int cc=0; cc<CC; cc++)
            acc += bq[l*PC + h*CC + cc] * Wk[((size_t)l*PC + h*CC + cc)*CC + tid];
        g_bqk[l*PC + h*CC + tid] = acc;
    } else if(bid < 10020){
        int idx = (bid-4644)*128 + tid;          // over LL*CC*KB
        int l = idx / (CC*KB);
        int j = (idx / KB) % CC;
        int c = idx % KB;
        float v;
        if(c < PC){
            int h = c >> 7, cp = c & 127;
            v = Wv[((size_t)l*PC + h*CC + j)*CC + cp] * (1.f/HH);
        } else {
            v = Ws[((size_t)l*CC + j)*CC + (c - PC)];
        }
        size_t o = ((size_t)l*CC + j)*KB + c;
        __nv_bfloat16 hi = __float2bfloat16(v);
        g_WBh[o] = hi;
        g_WBl[o] = __float2bfloat16(v - __bfloat162float(hi));
    } else if(bid < 10276){
        int i = (bid-10020)*128 + tid;
        g_deg[i]=0; g_cnt[i]=0;
    } else {
        int i = (bid-10276)*128 + tid;           // LL*CC
        int l = i >> 7, j = i & 127;
        float a = 0.f;
        #pragma unroll
        for(int h=0;h<HH;h++) a += bv[l*PC + h*CC + j];
        g_bvm[i] = a * (1.f/HH);
    }
}

// ---------------- CSR build --------------------------------------------------
__global__ void hist_kernel(const int* __restrict__ dst){
    int e = blockIdx.x*blockDim.x + threadIdx.x;
    if(e < EE) atomicAdd(&g_deg[dst[e]], 1);
}
__global__ void scan_kernel(){
    __shared__ int sh[1024];
    __shared__ int sbase;
    int tid = threadIdx.x;
    if(tid==0){ sbase = 0; g_off[0] = 0; }
    __syncthreads();
    for(int chunk=0; chunk<NN/1024; chunk++){
        int idx = chunk*1024 + tid;
        sh[tid] = g_deg[idx];
        __syncthreads();
        for(int o=1;o<1024;o<<=1){
            int t = (tid>=o) ? sh[tid-o] : 0;
            __syncthreads();
            sh[tid] += t;
            __syncthreads();
        }
        g_off[idx+1] = sbase + sh[tid];
        __syncthreads();
        if(tid==1023) sbase += sh[1023];
        __syncthreads();
    }
}
__global__ void scatter_kernel(const int* __restrict__ src, const int* __restrict__ dst){
    int e = blockIdx.x*blockDim.x + threadIdx.x;
    if(e < EE){
        int d = dst[e];
        int pos = g_off[d] + atomicAdd(&g_cnt[d], 1);
        g_srcs[pos] = src[e];
    }
}

// ---------------- embedding (+ bf16 split) -----------------------------------
__global__ void embed_kernel(const int* __restrict__ atoms, const float* __restrict__ embd){
    int i = blockIdx.x*blockDim.x + threadIdx.x;
    int n = i >> 7, c = i & 127;
    float v = embd[atoms[n]*CC + c];
    g_x[i] = v;
    __nv_bfloat16 h = __float2bfloat16(v);
    g_xh[i] = h;
    g_xl[i] = __float2bfloat16(v - __bfloat162float(h));
}

// ---------------- MMA / LDSM macros ------------------------------------------
#define MMA16816(d, a, b) asm volatile( \
    "mma.sync.aligned.m16n8k16.row.col.f32.bf16.bf16.f32 " \
    "{%0,%1,%2,%3}, {%4,%5,%6,%7}, {%8,%9}, {%0,%1,%2,%3};" \
    : "+f"(d[0]),"+f"(d[1]),"+f"(d[2]),"+f"(d[3]) \
    : "r"(a[0]),"r"(a[1]),"r"(a[2]),"r"(a[3]), "r"(b[0]),"r"(b[1]))

#define LDSM_X4(R0,R1,R2,R3,A) asm volatile( \
    "ldmatrix.sync.aligned.m8n8.x4.shared.b16 {%0,%1,%2,%3}, [%4];" \
    : "=r"(R0),"=r"(R1),"=r"(R2),"=r"(R3) : "r"(A))

__device__ __forceinline__ unsigned smem_u32p(const void* p){
    return (unsigned)__cvta_generic_to_shared(p);
}

// ---------------- GEMM A: p = (x @ Wqk^T + bqk)/sqrt(C), 128x128 tiles -------
__global__ __launch_bounds__(256) void gemm_p(int layer)
{
    __shared__ __nv_bfloat16 sA[128][72], sB[128][72];
    int col0 = blockIdx.x * 128;
    int row0 = blockIdx.y * 128;
    int tid = threadIdx.x, warp = tid >> 5, lane = tid & 31;
    int wm = warp >> 2, wn = warp & 3;      // 2 x 4 warp grid
    int wr0 = wm * 64, wc0 = wn * 32;       // warp tile 64 x 32
    int gid = lane >> 2, tig = lane & 3;

    float acc[4][4][4];
    #pragma unroll
    for(int i=0;i<4;i++)
        #pragma unroll
        for(int j=0;j<4;j++)
            #pragma unroll
            for(int t=0;t<4;t++) acc[i][j][t] = 0.f;

    int lr = tid >> 1;              // 0..127
    int lc = (tid & 1) * 32;        // 0 or 32 (each thread: 32 bf16 = 4 uint4)
    const __nv_bfloat16* Ag = &g_xh[(size_t)(row0+lr)*CC + lc];
    const __nv_bfloat16* Bg = &g_WAh[((size_t)layer*PC + col0 + lr)*CC + lc];

    unsigned aAddr[4], bAddr[2];
    #pragma unroll
    for(int i=0;i<4;i++)
        aAddr[i] = smem_u32p(&sA[wr0 + i*16 + (lane & 15)][(lane >> 4) * 8]);
    #pragma unroll
    for(int g=0; g<2; g++)
        bAddr[g] = smem_u32p(&sB[wc0 + g*16 + (lane & 7) + ((lane >> 4) << 3)][((lane >> 3) & 1) * 8]);

    #pragma unroll
    for(int kit=0; kit<2; kit++){
        int k0 = kit * 64;
        #pragma unroll
        for(int q=0;q<4;q++){
            *(uint4*)&sA[lr][lc + 8*q] = *(const uint4*)(Ag + k0 + 8*q);
            *(uint4*)&sB[lr][lc + 8*q] = *(const uint4*)(Bg + k0 + 8*q);
        }
        __syncthreads();
        #pragma unroll
        for(int ks=0; ks<64; ks+=16){
            unsigned a_[4][4], b_[4][2];
            #pragma unroll
            for(int i=0;i<4;i++)
                LDSM_X4(a_[i][0], a_[i][1], a_[i][2], a_[i][3], aAddr[i] + ks*2);
            #pragma unroll
            for(int g=0; g<2; g++)
                LDSM_X4(b_[g*2][0], b_[g*2][1], b_[g*2+1][0], b_[g*2+1][1], bAddr[g] + ks*2);
            #pragma unroll
            for(int i=0;i<4;i++)
                #pragma unroll
                for(int j=0;j<4;j++)
                    MMA16816(acc[i][j], a_[i], b_[j]);
        }
        __syncthreads();
    }

    const float invsq = 0.08838834764831845f;  // 1/sqrt(128)
    #pragma unroll
    for(int i=0;i<4;i++){
        int r = row0 + wr0 + i*16 + gid;
        #pragma unroll
        for(int j=0;j<4;j++){
            int c = col0 + wc0 + j*8 + 2*tig;
            float b0 = g_bqk[layer*PC + c], b1 = g_bqk[layer*PC + c + 1];
            *(__nv_bfloat162*)&g_pb[(size_t)r*PC + c] = __nv_bfloat162(
                __float2bfloat16((acc[i][j][0] + b0)*invsq),
                __float2bfloat16((acc[i][j][1] + b1)*invsq));
            *(__nv_bfloat162*)&g_pb[(size_t)(r+8)*PC + c] = __nv_bfloat162(
                __float2bfloat16((acc[i][j][2] + b0)*invsq),
                __float2bfloat16((acc[i][j][3] + b1)*invsq));
        }
    }
}

// ---------------- attention: single-pass online softmax, aggregate x ---------
__global__ __launch_bounds__(256) void attn_kernel(int parity)
{
    const float4* x4 = (const float4*)(parity ? g_xn : g_x);
    int warp = (blockIdx.x*blockDim.x + threadIdx.x) >> 5;
    int lane = threadIdx.x & 31;
    if(warp >= NN) return;
    int d = warp;

    const __nv_bfloat162* pb = (const __nv_bfloat162*)&g_pb[(size_t)d*PC];
    float4 p[HH];
    #pragma unroll
    for(int h=0;h<HH;h++){
        float2 f0 = __bfloat1622float2(pb[h*64 + lane*2]);
        float2 f1 = __bfloat1622float2(pb[h*64 + lane*2 + 1]);
        p[h] = make_float4(f0.x, f0.y, f1.x, f1.y);
    }

    int e0 = g_off[d], e1 = g_off[d+1];
    float m[HH], den[HH];
    float4 y[HH];
    #pragma unroll
    for(int h=0;h<HH;h++){ m[h]=-1e30f; den[h]=0.f; y[h]=make_float4(0.f,0.f,0.f,0.f); }

    for(int t=e0; t<e1; t++){
        int s = g_srcs[t];
        float4 xv = x4[(size_t)s*32 + lane];
        float dot[HH];
        #pragma unroll
        for(int h=0;h<HH;h++)
            dot[h] = p[h].x*xv.x + p[h].y*xv.y + p[h].z*xv.z + p[h].w*xv.w;
        #pragma unroll
        for(int h=0;h<HH;h++){
            #pragma unroll
            for(int o=16;o>0;o>>=1) dot[h] += __shfl_xor_sync(0xffffffffu, dot[h], o);
        }
        #pragma unroll
        for(int h=0;h<HH;h++){
            float mn = fmaxf(m[h], dot[h]);
            float corr = __expf(m[h] - mn);
            float ex   = __expf(dot[h] - mn);
            den[h] = den[h]*corr + ex;
            y[h].x = y[h].x*corr + ex*xv.x;
            y[h].y = y[h].y*corr + ex*xv.y;
            y[h].z = y[h].z*corr + ex*xv.z;
            y[h].w = y[h].w*corr + ex*xv.w;
            m[h] = mn;
        }
    }

    size_t base = (size_t)d*PC;
    #pragma unroll
    for(int h=0;h<HH;h++){
        float r = (den[h] > 0.f) ? 1.f/den[h] : 0.f;
        float v0=y[h].x*r, v1=y[h].y*r, v2=y[h].z*r, v3=y[h].w*r;
        int c = h*CC + lane*4;
        __nv_bfloat16 h0=__float2bfloat16(v0), h1=__float2bfloat16(v1);
        __nv_bfloat16 h2=__float2bfloat16(v2), h3=__float2bfloat16(v3);
        *(__nv_bfloat162*)&g_yh[base+c]   = __nv_bfloat162(h0, h1);
        *(__nv_bfloat162*)&g_yh[base+c+2] = __nv_bfloat162(h2, h3);
        __nv_bfloat16 l0=__float2bfloat16(v0-__bfloat162float(h0));
        __nv_bfloat16 l1=__float2bfloat16(v1-__bfloat162float(h1));
        __nv_bfloat16 l2=__float2bfloat16(v2-__bfloat162float(h2));
        __nv_bfloat16 l3=__float2bfloat16(v3-__bfloat162float(h3));
        *(__nv_bfloat162*)&g_yl[base+c]   = __nv_bfloat162(l0, l1);
        *(__nv_bfloat162*)&g_yl[base+c+2] = __nv_bfloat162(l2, l3);
    }
}

// ---------------- GEMM B: out = [y|x] @ WB^T (+bias,+res) -> LN -> ReLU ------
// 128x128 tile, K=896 in 14 chunks of 64; 3-pass hi/lo; dynamic smem:
// Ah | Al | Bh | Bl, each [128][72] bf16 (18432 B) -> 73728 B; epilogue C fp32
// [128][132] (67584 B) reuses the same buffer.
#define GB_SEG 18432
#define GB_SMEM (4*GB_SEG)
__global__ __launch_bounds__(256,2) void gemm_b(
    int layer, int parity,
    const float* __restrict__ bs, const float* __restrict__ lg, const float* __restrict__ lb)
{
    extern __shared__ char dsm[];
    __nv_bfloat16 (*Ah)[72] = (__nv_bfloat16(*)[72])(dsm);
    __nv_bfloat16 (*Al)[72] = (__nv_bfloat16(*)[72])(dsm + GB_SEG);
    __nv_bfloat16 (*Bh)[72] = (__nv_bfloat16(*)[72])(dsm + 2*GB_SEG);
    __nv_bfloat16 (*Bl)[72] = (__nv_bfloat16(*)[72])(dsm + 3*GB_SEG);

    const float* xold = parity ? g_xn : g_x;
    float*       xo   = parity ? g_x  : g_xn;
    int row0 = blockIdx.x * 128;
    int tid = threadIdx.x, warp = tid >> 5, lane = tid & 31;
    int wm = warp >> 2, wn = warp & 3;
    int wr0 = wm * 64, wc0 = wn * 32;
    int gid = lane >> 2, tig = lane & 3;

    float acc[4][4][4];
    #pragma unroll
    for(int i=0;i<4;i++)
        #pragma unroll
        for(int j=0;j<4;j++)
            #pragma unroll
            for(int t=0;t<4;t++) acc[i][j][t] = 0.f;

    int lr = tid >> 1;
    int lc = (tid & 1) * 32;

    unsigned aAddrH[4], aAddrL[4], bAddrH[2], bAddrL[2];
    {
        int arow = lane & 15, ak = (lane >> 4) * 8;
        #pragma unroll
        for(int i=0;i<4;i++){
            aAddrH[i] = smem_u32p(&Ah[wr0 + i*16 + arow][ak]);
            aAddrL[i] = smem_u32p(&Al[wr0 + i*16 + arow][ak]);
        }
        int bcol = (lane & 7) + ((lane >> 4) << 3);
        int bk = ((lane >> 3) & 1) * 8;
        #pragma unroll
        for(int g=0; g<2; g++){
            bAddrH[g] = smem_u32p(&Bh[wc0 + g*16 + bcol][bk]);
            bAddrL[g] = smem_u32p(&Bl[wc0 + g*16 + bcol][bk]);
        }
    }

    for(int s=0; s<14; s++){
        int k0 = s * 64;
        const __nv_bfloat16 *ah, *al;
        if(k0 < PC){
            ah = &g_yh[(size_t)(row0+lr)*PC + k0 + lc];
            al = &g_yl[(size_t)(row0+lr)*PC + k0 + lc];
        } else {
            ah = &g_xh[(size_t)(row0+lr)*CC + (k0 - PC) + lc];
            al = &g_xl[(size_t)(row0+lr)*CC + (k0 - PC) + lc];
        }
        const __nv_bfloat16* bhg = &g_WBh[((size_t)layer*CC + lr)*KB + k0 + lc];
        const __nv_bfloat16* blg = &g_WBl[((size_t)layer*CC + lr)*KB + k0 + lc];
        #pragma unroll
        for(int q=0;q<4;q++){
            *(uint4*)&Ah[lr][lc + 8*q] = *(const uint4*)(ah + 8*q);
            *(uint4*)&Al[lr][lc + 8*q] = *(const uint4*)(al + 8*q);
            *(uint4*)&Bh[lr][lc + 8*q] = *(const uint4*)(bhg + 8*q);
            *(uint4*)&Bl[lr][lc + 8*q] = *(const uint4*)(blg + 8*q);
        }
        __syncthreads();

        #pragma unroll
        for(int ks=0; ks<64; ks+=16){
            unsigned bh_[4][2], bl_[4][2], a_[4][4];
            #pragma unroll
            for(int g=0; g<2; g++){
                LDSM_X4(bh_[g*2][0], bh_[g*2][1], bh_[g*2+1][0], bh_[g*2+1][1], bAddrH[g] + ks*2);
                LDSM_X4(bl_[g*2][0], bl_[g*2][1], bl_[g*2+1][0], bl_[g*2+1][1], bAddrL[g] + ks*2);
            }
            #pragma unroll
            for(int i=0;i<4;i++)
                LDSM_X4(a_[i][0], a_[i][1], a_[i][2], a_[i][3], aAddrH[i] + ks*2);
            #pragma unroll
            for(int i=0;i<4;i++)
                #pragma unroll
                for(int j=0;j<4;j++){
                    MMA16816(acc[i][j], a_[i], bh_[j]);
                    MMA16816(acc[i][j], a_[i], bl_[j]);
                }
            #pragma unroll
            for(int i=0;i<4;i++)
                LDSM_X4(a_[i][0], a_[i][1], a_[i][2], a_[i][3], aAddrL[i] + ks*2);
            #pragma unroll
            for(int i=0;i<4;i++)
                #pragma unroll
                for(int j=0;j<4;j++)
                    MMA16816(acc[i][j], a_[i], bh_[j]);
        }
        __syncthreads();
    }

    // dump accumulators to smem C (stride 132 floats)
    float* Csm = (float*)dsm;
    #pragma unroll
    for(int i=0;i<4;i++){
        int r = wr0 + i*16 + gid;
        #pragma unroll
        for(int j=0;j<4;j++){
            int c = wc0 + j*8 + 2*tig;
            Csm[r*132 + c]       = acc[i][j][0];
            Csm[r*132 + c + 1]   = acc[i][j][1];
            Csm[(r+8)*132 + c]   = acc[i][j][2];
            Csm[(r+8)*132 + c+1] = acc[i][j][3];
        }
    }
    __syncthreads();

    // epilogue: 2 threads per row, 64 channels each
    {
        int row = tid >> 1, half = tid & 1;
        int n = row0 + row;
        float* Crow = Csm + row*132 + half*64;
        float flag = (g_off[n+1] > g_off[n]) ? 1.f : 0.f;
        const float* xr = &xold[(size_t)n*CC + half*64];
        int cb = half*64;
        float s1 = 0.f;
        #pragma unroll 8
        for(int k=0;k<64;k++){
            int c = cb + k;
            float v = Crow[k] + bs[c] + flag*g_bvm[layer*CC + c] + xr[k];
            Crow[k] = v;
            s1 += v;
        }
        s1 += __shfl_xor_sync(0xffffffffu, s1, 1);
        float mean = s1 * (1.f/CC);
        float s2 = 0.f;
        #pragma unroll 8
        for(int k=0;k<64;k++){ float dv = Crow[k]-mean; s2 += dv*dv; }
        s2 += __shfl_xor_sync(0xffffffffu, s2, 1);
        float inv = rsqrtf(s2*(1.f/CC) + 1e-5f);
        #pragma unroll 4
        for(int k=0;k<64;k+=2){
            int c = cb + k;
            float y0 = (Crow[k]  -mean)*inv*lg[c]   + lb[c];
            float y1 = (Crow[k+1]-mean)*inv*lg[c+1] + lb[c+1];
            y0 = fmaxf(y0, 0.f); y1 = fmaxf(y1, 0.f);
            *(float2*)&xo[(size_t)n*CC + c] = make_float2(y0, y1);
            __nv_bfloat16 h0 = __float2bfloat16(y0), h1 = __float2bfloat16(y1);
            *(__nv_bfloat162*)&g_xh[(size_t)n*CC + c] = __nv_bfloat162(h0, h1);
            *(__nv_bfloat162*)&g_xl[(size_t)n*CC + c] = __nv_bfloat162(
                __float2bfloat16(y0 - __bfloat162float(h0)),
                __float2bfloat16(y1 - __bfloat162float(h1)));
        }
    }
}

// ---------------- output MLP on supernodes -----------------------------------
__global__ void mlp_kernel(int sel, const float* __restrict__ W, const float* __restrict__ b){
    const float* in  = sel ? g_m1 : g_x;
    float*       out = sel ? g_m2 : g_m1;
    __shared__ float row[CC];
    int g = blockIdx.x, c = threadIdx.x;
    row[c] = in[(size_t)g*CC + c];
    __syncthreads();
    float acc = b[c];
    const float* w = &W[(size_t)c*CC];
    #pragma unroll 8
    for(int k2=0;k2<CC;k2++) acc += row[k2]*w[k2];
    out[(size_t)g*CC + c] = fmaxf(acc, 0.f);
}

__global__ void final_kernel(const float* __restrict__ Wp, const float* __restrict__ bp,
                             float* __restrict__ out){
    int warp = (blockIdx.x*blockDim.x + threadIdx.x) >> 5;
    int lane = threadIdx.x & 31;
    if(warp >= GG) return;
    float a = 0.f;
    #pragma unroll
    for(int i=0;i<4;i++){
        int c = lane + 32*i;
        a += g_m2[(size_t)warp*CC + c] * Wp[c];
    }
    #pragma unroll
    for(int o=16;o>0;o>>=1) a += __shfl_xor_sync(0xffffffffu, a, o);
    if(lane==0) out[warp] = a + bp[0];
}

// ---------------- launch -----------------------------------------------------
extern "C" void kernel_launch(void* const* d_in, const int* in_sizes, int n_in,
                              void* d_out, int out_size)
{
    const int*   atoms = (const int*)d_in[0];
    const int*   ei    = (const int*)d_in[1];
    const int*   src   = ei;
    const int*   dstp  = ei + EE;
    const float* embd  = (const float*)d_in[2];
    const float* Wq    = (const float*)d_in[3];
    const float* bq    = (const float*)d_in[4];
    const float* Wk    = (const float*)d_in[5];
    const float* bk    = (const float*)d_in[6];  (void)bk; // softmax-invariant
    const float* Wv    = (const float*)d_in[7];
    const float* bv    = (const float*)d_in[8];
    const float* Ws    = (const float*)d_in[9];
    const float* bs    = (const float*)d_in[10];
    const float* lg    = (const float*)d_in[11];
    const float* lb    = (const float*)d_in[12];
    const float* Wlin  = (const float*)d_in[13];
    const float* blin  = (const float*)d_in[14];
    const float* Wp    = (const float*)d_in[15];
    const float* bp    = (const float*)d_in[16];
    float* out = (float*)d_out;

    cudaFuncSetAttribute(gemm_b, cudaFuncAttributeMaxDynamicSharedMemorySize, GB_SMEM);

    // order chosen so my 4th launch is gemm_p(l=0) (ncu target)
    prep_kernel<<<10282, 128>>>(Wq, Wk, Wv, Ws, bq, bv);           // 1
    embed_kernel<<<NN*CC/256, 256>>>(atoms, embd);                 // 2
    hist_kernel<<<EE/256, 256>>>(dstp);                            // 3
    gemm_p<<<dim3(PC/128, NN/128), 256>>>(0);                      // 4 <- ncu target
    scan_kernel<<<1, 1024>>>();                                    // 5
    scatter_kernel<<<EE/256, 256>>>(src, dstp);                    // 6
    attn_kernel<<<NN/8, 256>>>(0);                                 // 7
    gemm_b<<<NN/128, 256, GB_SMEM>>>(0, 0, bs, lg, lb);            // 8

    for(int l=1; l<LL; l++){
        int parity = l & 1;
        gemm_p<<<dim3(PC/128, NN/128), 256>>>(l);
        attn_kernel<<<NN/8, 256>>>(parity);
        gemm_b<<<NN/128, 256, GB_SMEM>>>(l, parity, bs + (size_t)l*CC,
                                         lg + (size_t)l*CC, lb + (size_t)l*CC);
    }

    mlp_kernel<<<GG, CC>>>(0, Wlin,         blin);
    mlp_kernel<<<GG, CC>>>(1, Wlin + CC*CC, blin + CC);
    final_kernel<<<GG*32/256, 256>>>(Wp, bp, out);
}